// round 11
// baseline (speedup 1.0000x reference)
#include <cuda_runtime.h>
#include <cuda_bf16.h>
#include <cstdint>
#include <math.h>

#define N 8192
#define EDIM 128
#define WFEAT 128
#define SLOPE 0.01f
#define NEGINF (-3.0e38f)
#define L2E 1.4426950408889634f

// ---------------- device scratch ----------------
__device__ float g_h[(size_t)N * WFEAT];
__device__ __nv_bfloat16 g_h16_hi[(size_t)N * WFEAT];
__device__ __nv_bfloat16 g_h16_lo[(size_t)N * WFEAT];
__device__ float g_fsrc[N];
__device__ float g_fdst[N];
__device__ float g_rowC[N];
__device__ uint32_t g_mask[(size_t)N * 256];     // packed (adj+self)>0, 8MB
__device__ float g_pmax[64 * WFEAT];

// ---------------- helpers ----------------
__device__ __forceinline__ uint32_t smem_u32(const void* p) {
    uint32_t a;
    asm("{ .reg .u64 t; cvta.to.shared.u64 t, %1; cvt.u32.u64 %0, t; }" : "=r"(a) : "l"(p));
    return a;
}
__device__ __forceinline__ uint32_t pack2(float lo, float hi) {
    uint32_t r;
    asm("cvt.rn.bf16x2.f32 %0, %1, %2;" : "=r"(r) : "f"(hi), "f"(lo));
    return r;
}
__device__ __forceinline__ void cp16(uint32_t dst, const void* src) {
    asm volatile("cp.async.cg.shared.global [%0], [%1], 16;" :: "r"(dst), "l"(src));
}
__device__ __forceinline__ void cp_commit() {
    asm volatile("cp.async.commit_group;");
}
__device__ __forceinline__ void cp_wait0() {
    asm volatile("cp.async.wait_group 0;");
}
__device__ __forceinline__ void ldsm_x4(uint32_t* r, uint32_t addr) {
    asm volatile("ldmatrix.sync.aligned.m8n8.x4.shared.b16 {%0,%1,%2,%3}, [%4];"
                 : "=r"(r[0]), "=r"(r[1]), "=r"(r[2]), "=r"(r[3]) : "r"(addr));
}
__device__ __forceinline__ void ldsm_x4_t(uint32_t* r, uint32_t addr) {
    asm volatile("ldmatrix.sync.aligned.m8n8.x4.trans.shared.b16 {%0,%1,%2,%3}, [%4];"
                 : "=r"(r[0]), "=r"(r[1]), "=r"(r[2]), "=r"(r[3]) : "r"(addr));
}
__device__ __forceinline__ void mma16816(float* d, const uint32_t* a, const uint32_t* b) {
    asm volatile(
        "mma.sync.aligned.m16n8k16.row.col.f32.bf16.bf16.f32 "
        "{%0,%1,%2,%3}, {%4,%5,%6,%7}, {%8,%9}, {%0,%1,%2,%3};"
        : "+f"(d[0]), "+f"(d[1]), "+f"(d[2]), "+f"(d[3])
        : "r"(a[0]), "r"(a[1]), "r"(a[2]), "r"(a[3]), "r"(b[0]), "r"(b[1]));
}

// ---------------- K1: h = emb[inSen] @ W (+ bf16 hi/lo) ----------------
__global__ __launch_bounds__(128) void k1_proj(const int* __restrict__ inSen,
                                               const float* __restrict__ emb,
                                               const float* __restrict__ W) {
    __shared__ float Ws[64][128];
    __shared__ float wv[16][64];
    __shared__ int   sIdx[16];

    const int tid = threadIdx.x;
    const int i0  = blockIdx.x * 16;

    if (tid < 16) sIdx[tid] = inSen[i0 + tid];
    __syncthreads();

    float acc[16];
#pragma unroll
    for (int r = 0; r < 16; r++) acc[r] = 0.f;

    const int r  = tid >> 3;
    const int p0 = (tid & 7) * 8;

    for (int kc = 0; kc < EDIM; kc += 64) {
#pragma unroll 8
        for (int dd = 0; dd < 64; dd++)
            Ws[dd][tid] = W[(size_t)(kc + dd) * WFEAT + tid];
        {
            const float* er = emb + (size_t)sIdx[r] * EDIM + kc;
#pragma unroll
            for (int p = 0; p < 8; p++) wv[r][p0 + p] = er[p0 + p];
        }
        __syncthreads();
#pragma unroll 16
        for (int dd = 0; dd < 64; dd++) {
            const float w = Ws[dd][tid];
#pragma unroll
            for (int rr = 0; rr < 16; rr++) acc[rr] += wv[rr][dd] * w;
        }
        __syncthreads();
    }
#pragma unroll
    for (int rr = 0; rr < 16; rr++) {
        const float v = acc[rr];
        const size_t idx = (size_t)(i0 + rr) * WFEAT + tid;
        g_h[idx] = v;
        __nv_bfloat16 hb = __float2bfloat16(v);
        g_h16_hi[idx] = hb;
        g_h16_lo[idx] = __float2bfloat16(v - __bfloat162float(hb));
    }
}

// ---------------- Kf ----------------
__global__ __launch_bounds__(128) void kf_feat(const float* __restrict__ a_src,
                                               const float* __restrict__ a_dst) {
    const int i = blockIdx.x;
    const int tid = threadIdx.x;
    const float hv = g_h[(size_t)i * WFEAT + tid];
    float ps = hv * a_src[tid];
    float pd = hv * a_dst[tid];
#pragma unroll
    for (int off = 16; off > 0; off >>= 1) {
        ps += __shfl_xor_sync(0xffffffffu, ps, off);
        pd += __shfl_xor_sync(0xffffffffu, pd, off);
    }
    __shared__ float rs[4], rd[4];
    const int w = tid >> 5, l = tid & 31;
    if (l == 0) { rs[w] = ps; rd[w] = pd; }
    __syncthreads();
    if (tid == 0) g_fsrc[i] = rs[0] + rs[1] + rs[2] + rs[3];
    if (tid == 1) g_fdst[i] = rd[0] + rd[1] + rd[2] + rd[3];
}

// ---------------- K2: row stats + packed mask ----------------
__global__ __launch_bounds__(256) void k2_stats(const int* __restrict__ adj,
                                                const int* __restrict__ selfLinkP) {
    const int i   = blockIdx.x;
    const int tid = threadIdx.x;
    const int lane = tid & 31;
    const int selfLink = *selfLinkP;
    const float si = g_fsrc[i];

    float v[32];
    float tm = NEGINF;
#pragma unroll
    for (int k = 0; k < 32; k++) {
        const int j = tid + (k << 8);
        const int a = __ldg(&adj[(size_t)i * N + j]);
        const int m = a + ((j == i) ? selfLink : 0);
        const float x = si + __ldg(&g_fdst[j]);
        const float lk = fmaxf(x, SLOPE * x);
        const float val = (m > 0) ? lk : -1e9f;
        v[k] = val;
        tm = fmaxf(tm, val);
        const uint32_t bal = __ballot_sync(0xffffffffu, m > 0);
        if (lane == 0) g_mask[(size_t)i * 256 + (tid >> 5) + (k << 3)] = bal;
    }
    __shared__ float smax[8];
#pragma unroll
    for (int off = 16; off > 0; off >>= 1) tm = fmaxf(tm, __shfl_xor_sync(0xffffffffu, tm, off));
    if ((tid & 31) == 0) smax[tid >> 5] = tm;
    __syncthreads();
    if (tid < 32) {
        float z = (tid < 8) ? smax[tid] : NEGINF;
#pragma unroll
        for (int off = 4; off > 0; off >>= 1) z = fmaxf(z, __shfl_xor_sync(0xffffffffu, z, off));
        if (tid == 0) smax[0] = z;
    }
    __syncthreads();
    const float M = smax[0];

    float ts = 0.f;
#pragma unroll
    for (int k = 0; k < 32; k++) ts += __expf(v[k] - M);
    __shared__ float ssum[8];
#pragma unroll
    for (int off = 16; off > 0; off >>= 1) ts += __shfl_xor_sync(0xffffffffu, ts, off);
    if ((tid & 31) == 0) ssum[tid >> 5] = ts;
    __syncthreads();
    if (tid == 0) {
        float S = 0.f;
#pragma unroll
        for (int w = 0; w < 8; w++) S += ssum[w];
        g_rowC[i] = fmaf(-M, L2E, -__log2f(S));
    }
}

// ---------------- K3: cross-chunk pipelined bitmask attention + HMMA ----------------
// smem (bytes): B hi/lo ring 2 stages [0, 2*34816); A hi/lo double [69632, +2*9216)
#define B_BUF 17408
#define B_STAGE 34816
#define SB_STRIDE 136
#define OFF_A 69632
#define A_BUF 4608
#define A_PAIR 9216
#define SA_STRIDE 72
#define K3_SMEM 88064
#define NCH (N / 64)

// one half (4 values) of stage-A for chunk cc -> A buffer at aBufOff (+att global write)
__device__ __forceinline__ void stage_a_half(char* smem, uint32_t aBufOff, int cc,
                                             float fs, float Cr,
                                             float* att_row, uint2 mw, float4 d4,
                                             int arow, int acol, int g) {
    const int jcol = acol + g * 4;
    const int jg = cc * 64 + jcol;
    const uint32_t w = (jcol & 32) ? mw.y : mw.x;
    const int sh = jcol & 31;

    float v0 = fs + d4.x, v1 = fs + d4.y, v2 = fs + d4.z, v3 = fs + d4.w;
    v0 = fmaxf(v0, SLOPE * v0);
    v1 = fmaxf(v1, SLOPE * v1);
    v2 = fmaxf(v2, SLOPE * v2);
    v3 = fmaxf(v3, SLOPE * v3);
    float r0 = (w & (1u << (sh + 0))) ? fmaf(v0, L2E, Cr) : -1e30f;
    float r1 = (w & (1u << (sh + 1))) ? fmaf(v1, L2E, Cr) : -1e30f;
    float r2 = (w & (1u << (sh + 2))) ? fmaf(v2, L2E, Cr) : -1e30f;
    float r3 = (w & (1u << (sh + 3))) ? fmaf(v3, L2E, Cr) : -1e30f;
    float a0, a1, a2, a3;
    asm("ex2.approx.f32 %0, %1;" : "=f"(a0) : "f"(r0));
    asm("ex2.approx.f32 %0, %1;" : "=f"(a1) : "f"(r1));
    asm("ex2.approx.f32 %0, %1;" : "=f"(a2) : "f"(r2));
    asm("ex2.approx.f32 %0, %1;" : "=f"(a3) : "f"(r3));

    __stcs((float4*)(att_row + jg), make_float4(a0, a1, a2, a3));

    const uint32_t h01 = pack2(a0, a1);
    const uint32_t h23 = pack2(a2, a3);
    const float l0 = a0 - __uint_as_float(h01 << 16);
    const float l1 = a1 - __uint_as_float(h01 & 0xFFFF0000u);
    const float l2 = a2 - __uint_as_float(h23 << 16);
    const float l3 = a3 - __uint_as_float(h23 & 0xFFFF0000u);
    const uint32_t q01 = pack2(l0, l1);
    const uint32_t q23 = pack2(l2, l3);
    const uint32_t ao = (arow * SA_STRIDE + jcol) * 2;
    *(uint2*)(smem + aBufOff + ao)         = make_uint2(h01, h23);
    *(uint2*)(smem + aBufOff + A_BUF + ao) = make_uint2(q01, q23);
}

__global__ __launch_bounds__(256, 2) void k3_hmma(float* __restrict__ att_out,
                                                  float* __restrict__ sen_out) {
    extern __shared__ char smem[];
    const uint32_t sb = smem_u32(smem);

    const int tid = threadIdx.x;
    const int wid = tid >> 5;
    const int lane = tid & 31;
    const int i0 = blockIdx.x * 32;

    // stage-A mapping: 8 threads per row, 8 cols each
    const int arow = tid >> 3;
    const int acol = (tid & 7) * 8;
    const int gi = i0 + arow;
    const float fs = g_fsrc[gi];
    const float Cr = g_rowC[gi];
    float* att_row = att_out + (size_t)gi * N;
    const uint2* mrow = (const uint2*)(g_mask + (size_t)gi * 256);

    // B cp.async mapping
    const int cprowB = tid >> 4;
    const int cpsegB = tid & 15;

    // MMA warp tiling
    const int warp_m = wid >> 2;
    const int warp_n = wid & 3;
    const int lrow = lane & 15;
    const int lgrp = lane >> 4;
    const uint32_t a_lane_off = ((warp_m * 16 + lrow) * SA_STRIDE + lgrp * 8) * 2;
    const uint32_t b_lane_off = (lrow * SB_STRIDE + warp_n * 32 + lgrp * 8) * 2;

    float acc[4][4];
#pragma unroll
    for (int nf = 0; nf < 4; nf++)
#pragma unroll
        for (int q = 0; q < 4; q++) acc[nf][q] = 0.f;

    // ---- prologue: prefetch B(0) into stage 0; stage-A(0) into A buf 0 ----
#pragma unroll
    for (int p = 0; p < 4; p++) {
        const int r = cprowB + p * 16;
        cp16(sb + r * 272 + cpsegB * 16,
             (const char*)g_h16_hi + ((size_t)r * WFEAT + cpsegB * 8) * 2);
        cp16(sb + B_BUF + r * 272 + cpsegB * 16,
             (const char*)g_h16_lo + ((size_t)r * WFEAT + cpsegB * 8) * 2);
    }
    cp_commit();
    {
        const uint2 mw0 = __ldg(&mrow[0]);
        const float4 d4a0 = __ldg((const float4*)&g_fdst[acol]);
        const float4 d4b0 = __ldg((const float4*)&g_fdst[acol + 4]);
        stage_a_half(smem, OFF_A, 0, fs, Cr, att_row, mw0, d4a0, arow, acol, 0);
        stage_a_half(smem, OFF_A, 0, fs, Cr, att_row, mw0, d4b0, arow, acol, 1);
    }

#pragma unroll 2
    for (int c = 0; c < NCH; c++) {
        const int b = c & 1;

        cp_wait0();        // own share of B(c) landed
        __syncthreads();   // all shares + A[b] visible; MMA(c-1) done -> buffers free

        // --- register-prefetch stage-A(c+1) operands (latency hidden by MMA ks0-1) ---
        uint2 mw_n = make_uint2(0u, 0u);
        float4 d4a_n = make_float4(0.f, 0.f, 0.f, 0.f);
        float4 d4b_n = d4a_n;
        const bool haveNext = (c + 1 < NCH);
        if (haveNext) {
            mw_n  = __ldg(&mrow[c + 1]);
            d4a_n = __ldg((const float4*)&g_fdst[(c + 1) * 64 + acol]);
            d4b_n = __ldg((const float4*)&g_fdst[(c + 1) * 64 + acol + 4]);
        }

        // --- prefetch B(c+1) into stage 1-b (last read by MMA(c-1)) ---
        if (haveNext) {
            const int jb = (c + 1) * 64;
            const uint32_t bs = sb + (1 - b) * B_STAGE;
#pragma unroll
            for (int p = 0; p < 4; p++) {
                const int r = cprowB + p * 16;
                cp16(bs + r * 272 + cpsegB * 16,
                     (const char*)g_h16_hi + ((size_t)(jb + r) * WFEAT + cpsegB * 8) * 2);
                cp16(bs + B_BUF + r * 272 + cpsegB * 16,
                     (const char*)g_h16_lo + ((size_t)(jb + r) * WFEAT + cpsegB * 8) * 2);
            }
        }
        cp_commit();

        // --- MMA(c) interleaved with stage-A(c+1) halves ---
        const uint32_t a_hi = sb + OFF_A + b * A_PAIR + a_lane_off;
        const uint32_t bh_base = sb + b * B_STAGE + b_lane_off;
        const uint32_t bl_base = bh_base + B_BUF;
        const uint32_t aNextOff = OFF_A + (1 - b) * A_PAIR;

#pragma unroll
        for (int ks = 0; ks < 2; ks++) {
            uint32_t ah[4], al[4], bh[2][4], bl[2][4];
            {
                const uint32_t aoff = (ks * 16) * 2;
                ldsm_x4(ah, a_hi + aoff);
                ldsm_x4(al, a_hi + A_BUF + aoff);
            }
#pragma unroll
            for (int pr = 0; pr < 2; pr++) {
                const uint32_t boff = (ks * 16 * SB_STRIDE + pr * 16) * 2;
                ldsm_x4_t(bh[pr], bh_base + boff);
                ldsm_x4_t(bl[pr], bl_base + boff);
            }
#pragma unroll
            for (int nf = 0; nf < 4; nf++) {
                const uint32_t* bhp = &bh[nf >> 1][(nf & 1) * 2];
                const uint32_t* blp = &bl[nf >> 1][(nf & 1) * 2];
                mma16816(acc[nf], ah, bhp);
                mma16816(acc[nf], al, bhp);
                mma16816(acc[nf], ah, blp);
            }
        }

        if (haveNext)
            stage_a_half(smem, aNextOff, c + 1, fs, Cr, att_row, mw_n, d4a_n, arow, acol, 0);

#pragma unroll
        for (int ks = 2; ks < 4; ks++) {
            uint32_t ah[4], al[4], bh[2][4], bl[2][4];
            {
                const uint32_t aoff = (ks * 16) * 2;
                ldsm_x4(ah, a_hi + aoff);
                ldsm_x4(al, a_hi + A_BUF + aoff);
            }
#pragma unroll
            for (int pr = 0; pr < 2; pr++) {
                const uint32_t boff = (ks * 16 * SB_STRIDE + pr * 16) * 2;
                ldsm_x4_t(bh[pr], bh_base + boff);
                ldsm_x4_t(bl[pr], bl_base + boff);
            }
#pragma unroll
            for (int nf = 0; nf < 4; nf++) {
                const uint32_t* bhp = &bh[nf >> 1][(nf & 1) * 2];
                const uint32_t* blp = &bl[nf >> 1][(nf & 1) * 2];
                mma16816(acc[nf], ah, bhp);
                mma16816(acc[nf], al, bhp);
                mma16816(acc[nf], ah, blp);
            }
        }

        if (haveNext)
            stage_a_half(smem, aNextOff, c + 1, fs, Cr, att_row, mw_n, d4b_n, arow, acol, 1);
    }

    // --- epilogue: 16x32 tile per warp ---
    const int grp = lane >> 2;
    const int tig = lane & 3;
#pragma unroll
    for (int nf = 0; nf < 4; nf++) {
        const int row0 = i0 + warp_m * 16 + grp;
        const int col  = warp_n * 32 + nf * 8 + tig * 2;
        __stcs((float2*)&sen_out[(size_t)row0 * WFEAT + col],
               make_float2(acc[nf][0], acc[nf][1]));
        __stcs((float2*)&sen_out[(size_t)(row0 + 8) * WFEAT + col],
               make_float2(acc[nf][2], acc[nf][3]));
    }
}

// ---------------- K4 ----------------
__global__ __launch_bounds__(128) void k4_pool_partial(const float* __restrict__ sen) {
    const int c = threadIdx.x;
    const int b = blockIdx.x;
    float m = NEGINF;
#pragma unroll 8
    for (int r = 0; r < 128; r++)
        m = fmaxf(m, __ldg(&sen[((size_t)b * 128 + r) * WFEAT + c]));
    g_pmax[b * WFEAT + c] = m;
}

// ---------------- K5 ----------------
__global__ __launch_bounds__(128) void k5_head(const float* __restrict__ cls_W,
                                               const float* __restrict__ cls_b,
                                               float* __restrict__ pool_out,
                                               float* __restrict__ lab_out) {
    const int c = threadIdx.x;
    __shared__ float pool[WFEAT];
    float m = NEGINF;
#pragma unroll
    for (int b = 0; b < 64; b++) m = fmaxf(m, g_pmax[b * WFEAT + c]);
    pool[c] = m;
    pool_out[c] = m;
    __syncthreads();
    if (c == 0) {
        float l0 = cls_b[0], l1 = cls_b[1];
#pragma unroll
        for (int k = 0; k < WFEAT; k++) {
            l0 += pool[k] * cls_W[2 * k];
            l1 += pool[k] * cls_W[2 * k + 1];
        }
        const float mm = fmaxf(l0, l1);
        const float e0 = __expf(l0 - mm), e1 = __expf(l1 - mm);
        const float inv = 1.0f / (e0 + e1);
        lab_out[0] = e0 * inv;
        lab_out[1] = e1 * inv;
    }
}

// ---------------- launch ----------------
extern "C" void kernel_launch(void* const* d_in, const int* in_sizes, int n_in,
                              void* d_out, int out_size) {
    const int*   inSen    = (const int*)d_in[0];
    const int*   adj      = (const int*)d_in[1];
    const int*   selfLink = (const int*)d_in[2];
    const float* emb      = (const float*)d_in[3];
    const float* W        = (const float*)d_in[4];
    const float* a_src    = (const float*)d_in[5];
    const float* a_dst    = (const float*)d_in[6];
    const float* cls_W    = (const float*)d_in[7];
    const float* cls_b    = (const float*)d_in[8];

    float* out      = (float*)d_out;
    float* pool_out = out;
    float* att_out  = out + WFEAT;
    float* sen_out  = att_out + (size_t)N * N;
    float* lab_out  = sen_out + (size_t)N * WFEAT;

    static int configured = 0;
    if (!configured) {
        cudaFuncSetAttribute(k3_hmma, cudaFuncAttributeMaxDynamicSharedMemorySize, K3_SMEM);
        configured = 1;
    }

    k1_proj<<<N / 16, 128>>>(inSen, emb, W);
    kf_feat<<<N, 128>>>(a_src, a_dst);
    k2_stats<<<N, 256>>>(adj, selfLink);
    k3_hmma<<<N / 32, 256, K3_SMEM>>>(att_out, sen_out);
    k4_pool_partial<<<64, 128>>>(sen_out);
    k5_head<<<1, 128>>>(cls_W, cls_b, pool_out, lab_out);
}

// round 12
// speedup vs baseline: 1.0192x; 1.0192x over previous
#include <cuda_runtime.h>
#include <cuda_bf16.h>
#include <cstdint>
#include <math.h>

#define N 8192
#define EDIM 128
#define WFEAT 128
#define SLOPE 0.01f
#define NEGINF (-3.0e38f)
#define L2E 1.4426950408889634f

// ---------------- device scratch ----------------
__device__ float g_h[(size_t)N * WFEAT];
__device__ __nv_bfloat16 g_h16_hi[(size_t)N * WFEAT];
__device__ __nv_bfloat16 g_h16_lo[(size_t)N * WFEAT];
__device__ float g_fsrc[N];
__device__ float g_fdst[N];
__device__ float g_rowC[N];
__device__ uint32_t g_mask[(size_t)N * 256];     // packed (adj+self)>0, 8MB
__device__ float g_pmax[64 * WFEAT];

// ---------------- helpers ----------------
__device__ __forceinline__ uint32_t smem_u32(const void* p) {
    uint32_t a;
    asm("{ .reg .u64 t; cvta.to.shared.u64 t, %1; cvt.u32.u64 %0, t; }" : "=r"(a) : "l"(p));
    return a;
}
__device__ __forceinline__ uint32_t pack2(float lo, float hi) {
    uint32_t r;
    asm("cvt.rn.bf16x2.f32 %0, %1, %2;" : "=r"(r) : "f"(hi), "f"(lo));
    return r;
}
__device__ __forceinline__ void cp16(uint32_t dst, const void* src) {
    asm volatile("cp.async.cg.shared.global [%0], [%1], 16;" :: "r"(dst), "l"(src));
}
__device__ __forceinline__ void cp_commit() {
    asm volatile("cp.async.commit_group;");
}
__device__ __forceinline__ void cp_wait0() {
    asm volatile("cp.async.wait_group 0;");
}
__device__ __forceinline__ void ldsm_x4(uint32_t* r, uint32_t addr) {
    asm volatile("ldmatrix.sync.aligned.m8n8.x4.shared.b16 {%0,%1,%2,%3}, [%4];"
                 : "=r"(r[0]), "=r"(r[1]), "=r"(r[2]), "=r"(r[3]) : "r"(addr));
}
__device__ __forceinline__ void ldsm_x4_t(uint32_t* r, uint32_t addr) {
    asm volatile("ldmatrix.sync.aligned.m8n8.x4.trans.shared.b16 {%0,%1,%2,%3}, [%4];"
                 : "=r"(r[0]), "=r"(r[1]), "=r"(r[2]), "=r"(r[3]) : "r"(addr));
}
__device__ __forceinline__ void mma16816(float* d, const uint32_t* a, const uint32_t* b) {
    asm volatile(
        "mma.sync.aligned.m16n8k16.row.col.f32.bf16.bf16.f32 "
        "{%0,%1,%2,%3}, {%4,%5,%6,%7}, {%8,%9}, {%0,%1,%2,%3};"
        : "+f"(d[0]), "+f"(d[1]), "+f"(d[2]), "+f"(d[3])
        : "r"(a[0]), "r"(a[1]), "r"(a[2]), "r"(a[3]), "r"(b[0]), "r"(b[1]));
}

// ---------------- K1: h = emb[inSen] @ W (+ bf16 hi/lo) ----------------
__global__ __launch_bounds__(128) void k1_proj(const int* __restrict__ inSen,
                                               const float* __restrict__ emb,
                                               const float* __restrict__ W) {
    __shared__ float Ws[64][128];
    __shared__ float wv[16][64];
    __shared__ int   sIdx[16];

    const int tid = threadIdx.x;
    const int i0  = blockIdx.x * 16;

    if (tid < 16) sIdx[tid] = inSen[i0 + tid];
    __syncthreads();

    float acc[16];
#pragma unroll
    for (int r = 0; r < 16; r++) acc[r] = 0.f;

    const int r  = tid >> 3;
    const int p0 = (tid & 7) * 8;

    for (int kc = 0; kc < EDIM; kc += 64) {
#pragma unroll 8
        for (int dd = 0; dd < 64; dd++)
            Ws[dd][tid] = W[(size_t)(kc + dd) * WFEAT + tid];
        {
            const float* er = emb + (size_t)sIdx[r] * EDIM + kc;
#pragma unroll
            for (int p = 0; p < 8; p++) wv[r][p0 + p] = er[p0 + p];
        }
        __syncthreads();
#pragma unroll 16
        for (int dd = 0; dd < 64; dd++) {
            const float w = Ws[dd][tid];
#pragma unroll
            for (int rr = 0; rr < 16; rr++) acc[rr] += wv[rr][dd] * w;
        }
        __syncthreads();
    }
#pragma unroll
    for (int rr = 0; rr < 16; rr++) {
        const float v = acc[rr];
        const size_t idx = (size_t)(i0 + rr) * WFEAT + tid;
        g_h[idx] = v;
        __nv_bfloat16 hb = __float2bfloat16(v);
        g_h16_hi[idx] = hb;
        g_h16_lo[idx] = __float2bfloat16(v - __bfloat162float(hb));
    }
}

// ---------------- Kf ----------------
__global__ __launch_bounds__(128) void kf_feat(const float* __restrict__ a_src,
                                               const float* __restrict__ a_dst) {
    const int i = blockIdx.x;
    const int tid = threadIdx.x;
    const float hv = g_h[(size_t)i * WFEAT + tid];
    float ps = hv * a_src[tid];
    float pd = hv * a_dst[tid];
#pragma unroll
    for (int off = 16; off > 0; off >>= 1) {
        ps += __shfl_xor_sync(0xffffffffu, ps, off);
        pd += __shfl_xor_sync(0xffffffffu, pd, off);
    }
    __shared__ float rs[4], rd[4];
    const int w = tid >> 5, l = tid & 31;
    if (l == 0) { rs[w] = ps; rd[w] = pd; }
    __syncthreads();
    if (tid == 0) g_fsrc[i] = rs[0] + rs[1] + rs[2] + rs[3];
    if (tid == 1) g_fdst[i] = rd[0] + rd[1] + rd[2] + rd[3];
}

// ---------------- K2: row stats + packed mask (vectorized) ----------------
__global__ __launch_bounds__(256) void k2_stats(const int* __restrict__ adj,
                                                const int* __restrict__ selfLinkP) {
    const int i   = blockIdx.x;
    const int tid = threadIdx.x;
    const int lane = tid & 31;
    const int selfLink = *selfLinkP;
    const float si = g_fsrc[i];

    float v[32];
    float tm = NEGINF;
    const int4* arow = (const int4*)(adj + (size_t)i * N);
#pragma unroll
    for (int k = 0; k < 8; k++) {
        const int idx4 = tid + (k << 8);          // 0..2047
        const int4 a = __ldg(arow + idx4);
        const int j0 = idx4 << 2;
        const float4 f4 = __ldg((const float4*)&g_fdst[j0]);

        const int m0 = a.x + ((j0 + 0) == i ? selfLink : 0);
        const int m1 = a.y + ((j0 + 1) == i ? selfLink : 0);
        const int m2 = a.z + ((j0 + 2) == i ? selfLink : 0);
        const int m3 = a.w + ((j0 + 3) == i ? selfLink : 0);

        float x0 = si + f4.x, x1 = si + f4.y, x2 = si + f4.z, x3 = si + f4.w;
        x0 = fmaxf(x0, SLOPE * x0);
        x1 = fmaxf(x1, SLOPE * x1);
        x2 = fmaxf(x2, SLOPE * x2);
        x3 = fmaxf(x3, SLOPE * x3);
        const float val0 = (m0 > 0) ? x0 : -1e9f;
        const float val1 = (m1 > 0) ? x1 : -1e9f;
        const float val2 = (m2 > 0) ? x2 : -1e9f;
        const float val3 = (m3 > 0) ? x3 : -1e9f;
        v[(k << 2) + 0] = val0;
        v[(k << 2) + 1] = val1;
        v[(k << 2) + 2] = val2;
        v[(k << 2) + 3] = val3;
        tm = fmaxf(tm, fmaxf(fmaxf(val0, val1), fmaxf(val2, val3)));

        // pack 4 mask bits; OR-reduce over 8-lane group -> one 32-bit word
        uint32_t wp = ((uint32_t)(m0 > 0) | ((uint32_t)(m1 > 0) << 1) |
                       ((uint32_t)(m2 > 0) << 2) | ((uint32_t)(m3 > 0) << 3))
                      << ((lane & 7) * 4);
        wp |= __shfl_xor_sync(0xffffffffu, wp, 1);
        wp |= __shfl_xor_sync(0xffffffffu, wp, 2);
        wp |= __shfl_xor_sync(0xffffffffu, wp, 4);
        if ((lane & 7) == 0)
            g_mask[(size_t)i * 256 + (idx4 >> 3)] = wp;
    }
    __shared__ float smax[8];
#pragma unroll
    for (int off = 16; off > 0; off >>= 1) tm = fmaxf(tm, __shfl_xor_sync(0xffffffffu, tm, off));
    if ((tid & 31) == 0) smax[tid >> 5] = tm;
    __syncthreads();
    if (tid < 32) {
        float z = (tid < 8) ? smax[tid] : NEGINF;
#pragma unroll
        for (int off = 4; off > 0; off >>= 1) z = fmaxf(z, __shfl_xor_sync(0xffffffffu, z, off));
        if (tid == 0) smax[0] = z;
    }
    __syncthreads();
    const float M = smax[0];

    float ts = 0.f;
#pragma unroll
    for (int k = 0; k < 32; k++) ts += __expf(v[k] - M);
    __shared__ float ssum[8];
#pragma unroll
    for (int off = 16; off > 0; off >>= 1) ts += __shfl_xor_sync(0xffffffffu, ts, off);
    if ((tid & 31) == 0) ssum[tid >> 5] = ts;
    __syncthreads();
    if (tid == 0) {
        float S = 0.f;
#pragma unroll
        for (int w = 0; w < 8; w++) S += ssum[w];
        g_rowC[i] = fmaf(-M, L2E, -__log2f(S));
    }
}

// ---------------- K3: cross-chunk pipelined bitmask attention + HMMA (R10) ----------------
// smem (bytes): B hi/lo ring 2 stages [0, 2*34816); A hi/lo double [69632, +2*9216)
#define B_BUF 17408
#define B_STAGE 34816
#define SB_STRIDE 136
#define OFF_A 69632
#define A_BUF 4608
#define A_PAIR 9216
#define SA_STRIDE 72
#define K3_SMEM 88064
#define NCH (N / 64)

// stage-A for chunk cc -> A buffer at aBufOff (+att global write); operands pre-loaded
__device__ __forceinline__ void stage_a(char* smem, uint32_t aBufOff, int cc,
                                        float fs, float Cr,
                                        float* att_row, uint2 mw,
                                        float4 d4a, float4 d4b,
                                        int arow, int acol) {
    const int jbase = cc * 64;
#pragma unroll
    for (int g = 0; g < 2; g++) {
        const int jcol = acol + g * 4;
        const int jg = jbase + jcol;
        const uint32_t w = (jcol & 32) ? mw.y : mw.x;
        const int sh = jcol & 31;
        const float4 d4 = g ? d4b : d4a;

        float v0 = fs + d4.x, v1 = fs + d4.y, v2 = fs + d4.z, v3 = fs + d4.w;
        v0 = fmaxf(v0, SLOPE * v0);
        v1 = fmaxf(v1, SLOPE * v1);
        v2 = fmaxf(v2, SLOPE * v2);
        v3 = fmaxf(v3, SLOPE * v3);
        float r0 = (w & (1u << (sh + 0))) ? fmaf(v0, L2E, Cr) : -1e30f;
        float r1 = (w & (1u << (sh + 1))) ? fmaf(v1, L2E, Cr) : -1e30f;
        float r2 = (w & (1u << (sh + 2))) ? fmaf(v2, L2E, Cr) : -1e30f;
        float r3 = (w & (1u << (sh + 3))) ? fmaf(v3, L2E, Cr) : -1e30f;
        float a0, a1, a2, a3;
        asm("ex2.approx.f32 %0, %1;" : "=f"(a0) : "f"(r0));
        asm("ex2.approx.f32 %0, %1;" : "=f"(a1) : "f"(r1));
        asm("ex2.approx.f32 %0, %1;" : "=f"(a2) : "f"(r2));
        asm("ex2.approx.f32 %0, %1;" : "=f"(a3) : "f"(r3));

        __stcs((float4*)(att_row + jg), make_float4(a0, a1, a2, a3));

        const uint32_t h01 = pack2(a0, a1);
        const uint32_t h23 = pack2(a2, a3);
        const float l0 = a0 - __uint_as_float(h01 << 16);
        const float l1 = a1 - __uint_as_float(h01 & 0xFFFF0000u);
        const float l2 = a2 - __uint_as_float(h23 << 16);
        const float l3 = a3 - __uint_as_float(h23 & 0xFFFF0000u);
        const uint32_t q01 = pack2(l0, l1);
        const uint32_t q23 = pack2(l2, l3);
        const uint32_t ao = (arow * SA_STRIDE + jcol) * 2;
        *(uint2*)(smem + aBufOff + ao)         = make_uint2(h01, h23);
        *(uint2*)(smem + aBufOff + A_BUF + ao) = make_uint2(q01, q23);
    }
}

__global__ __launch_bounds__(256, 2) void k3_hmma(float* __restrict__ att_out,
                                                  float* __restrict__ sen_out) {
    extern __shared__ char smem[];
    const uint32_t sb = smem_u32(smem);

    const int tid = threadIdx.x;
    const int wid = tid >> 5;
    const int lane = tid & 31;
    const int i0 = blockIdx.x * 32;

    // stage-A mapping: 8 threads per row, 8 cols each
    const int arow = tid >> 3;
    const int acol = (tid & 7) * 8;
    const int gi = i0 + arow;
    const float fs = g_fsrc[gi];
    const float Cr = g_rowC[gi];
    float* att_row = att_out + (size_t)gi * N;
    const uint2* mrow = (const uint2*)(g_mask + (size_t)gi * 256);

    // B cp.async mapping
    const int cprowB = tid >> 4;
    const int cpsegB = tid & 15;

    // MMA warp tiling
    const int warp_m = wid >> 2;
    const int warp_n = wid & 3;
    const int lrow = lane & 15;
    const int lgrp = lane >> 4;
    const uint32_t a_lane_off = ((warp_m * 16 + lrow) * SA_STRIDE + lgrp * 8) * 2;
    const uint32_t b_lane_off = (lrow * SB_STRIDE + warp_n * 32 + lgrp * 8) * 2;

    float acc[4][4];
#pragma unroll
    for (int nf = 0; nf < 4; nf++)
#pragma unroll
        for (int q = 0; q < 4; q++) acc[nf][q] = 0.f;

    // ---- prologue: prefetch B(0) into stage 0; stage-A(0) into A buf 0 ----
#pragma unroll
    for (int p = 0; p < 4; p++) {
        const int r = cprowB + p * 16;
        cp16(sb + r * 272 + cpsegB * 16,
             (const char*)g_h16_hi + ((size_t)r * WFEAT + cpsegB * 8) * 2);
        cp16(sb + B_BUF + r * 272 + cpsegB * 16,
             (const char*)g_h16_lo + ((size_t)r * WFEAT + cpsegB * 8) * 2);
    }
    cp_commit();
    {
        const uint2 mw0 = __ldg(&mrow[0]);
        const float4 d4a0 = __ldg((const float4*)&g_fdst[acol]);
        const float4 d4b0 = __ldg((const float4*)&g_fdst[acol + 4]);
        stage_a(smem, OFF_A, 0, fs, Cr, att_row, mw0, d4a0, d4b0, arow, acol);
    }

#pragma unroll 2
    for (int c = 0; c < NCH; c++) {
        const int b = c & 1;

        cp_wait0();        // own share of B(c) landed
        __syncthreads();   // all shares + A[b] visible; MMA(c-1) done -> buffers free

        // --- register-prefetch stage-A(c+1) operands (latency hidden by MMA) ---
        uint2 mw_n = make_uint2(0u, 0u);
        float4 d4a_n = make_float4(0.f, 0.f, 0.f, 0.f);
        float4 d4b_n = d4a_n;
        if (c + 1 < NCH) {
            mw_n  = __ldg(&mrow[c + 1]);
            d4a_n = __ldg((const float4*)&g_fdst[(c + 1) * 64 + acol]);
            d4b_n = __ldg((const float4*)&g_fdst[(c + 1) * 64 + acol + 4]);
        }

        // --- prefetch B(c+1) into stage 1-b (last read by MMA(c-1)) ---
        if (c + 1 < NCH) {
            const int jb = (c + 1) * 64;
            const uint32_t bs = sb + (1 - b) * B_STAGE;
#pragma unroll
            for (int p = 0; p < 4; p++) {
                const int r = cprowB + p * 16;
                cp16(bs + r * 272 + cpsegB * 16,
                     (const char*)g_h16_hi + ((size_t)(jb + r) * WFEAT + cpsegB * 8) * 2);
                cp16(bs + B_BUF + r * 272 + cpsegB * 16,
                     (const char*)g_h16_lo + ((size_t)(jb + r) * WFEAT + cpsegB * 8) * 2);
            }
        }
        cp_commit();

        // --- MMA(c): A from buf b, B from stage b ---
        const uint32_t a_hi = sb + OFF_A + b * A_PAIR + a_lane_off;
        const uint32_t bh_base = sb + b * B_STAGE + b_lane_off;
        const uint32_t bl_base = bh_base + B_BUF;
#pragma unroll
        for (int ks = 0; ks < 4; ks++) {
            uint32_t ah[4], al[4], bh[2][4], bl[2][4];
            {
                const uint32_t aoff = (ks * 16) * 2;
                ldsm_x4(ah, a_hi + aoff);
                ldsm_x4(al, a_hi + A_BUF + aoff);
            }
#pragma unroll
            for (int pr = 0; pr < 2; pr++) {
                const uint32_t boff = (ks * 16 * SB_STRIDE + pr * 16) * 2;
                ldsm_x4_t(bh[pr], bh_base + boff);
                ldsm_x4_t(bl[pr], bl_base + boff);
            }
#pragma unroll
            for (int nf = 0; nf < 4; nf++) {
                const uint32_t* bhp = &bh[nf >> 1][(nf & 1) * 2];
                const uint32_t* blp = &bl[nf >> 1][(nf & 1) * 2];
                mma16816(acc[nf], ah, bhp);
                mma16816(acc[nf], al, bhp);
                mma16816(acc[nf], ah, blp);
            }
        }

        // --- stage-A(c+1) into A buf 1-b (last read by MMA(c-1)) ---
        if (c + 1 < NCH)
            stage_a(smem, OFF_A + (1 - b) * A_PAIR, c + 1, fs, Cr,
                    att_row, mw_n, d4a_n, d4b_n, arow, acol);
    }

    // --- epilogue: 16x32 tile per warp ---
    const int grp = lane >> 2;
    const int tig = lane & 3;
#pragma unroll
    for (int nf = 0; nf < 4; nf++) {
        const int row0 = i0 + warp_m * 16 + grp;
        const int col  = warp_n * 32 + nf * 8 + tig * 2;
        __stcs((float2*)&sen_out[(size_t)row0 * WFEAT + col],
               make_float2(acc[nf][0], acc[nf][1]));
        __stcs((float2*)&sen_out[(size_t)(row0 + 8) * WFEAT + col],
               make_float2(acc[nf][2], acc[nf][3]));
    }
}

// ---------------- K4 ----------------
__global__ __launch_bounds__(128) void k4_pool_partial(const float* __restrict__ sen) {
    const int c = threadIdx.x;
    const int b = blockIdx.x;
    float m = NEGINF;
#pragma unroll 8
    for (int r = 0; r < 128; r++)
        m = fmaxf(m, __ldg(&sen[((size_t)b * 128 + r) * WFEAT + c]));
    g_pmax[b * WFEAT + c] = m;
}

// ---------------- K5 ----------------
__global__ __launch_bounds__(128) void k5_head(const float* __restrict__ cls_W,
                                               const float* __restrict__ cls_b,
                                               float* __restrict__ pool_out,
                                               float* __restrict__ lab_out) {
    const int c = threadIdx.x;
    __shared__ float pool[WFEAT];
    float m = NEGINF;
#pragma unroll
    for (int b = 0; b < 64; b++) m = fmaxf(m, g_pmax[b * WFEAT + c]);
    pool[c] = m;
    pool_out[c] = m;
    __syncthreads();
    if (c == 0) {
        float l0 = cls_b[0], l1 = cls_b[1];
#pragma unroll
        for (int k = 0; k < WFEAT; k++) {
            l0 += pool[k] * cls_W[2 * k];
            l1 += pool[k] * cls_W[2 * k + 1];
        }
        const float mm = fmaxf(l0, l1);
        const float e0 = __expf(l0 - mm), e1 = __expf(l1 - mm);
        const float inv = 1.0f / (e0 + e1);
        lab_out[0] = e0 * inv;
        lab_out[1] = e1 * inv;
    }
}

// ---------------- launch ----------------
extern "C" void kernel_launch(void* const* d_in, const int* in_sizes, int n_in,
                              void* d_out, int out_size) {
    const int*   inSen    = (const int*)d_in[0];
    const int*   adj      = (const int*)d_in[1];
    const int*   selfLink = (const int*)d_in[2];
    const float* emb      = (const float*)d_in[3];
    const float* W        = (const float*)d_in[4];
    const float* a_src    = (const float*)d_in[5];
    const float* a_dst    = (const float*)d_in[6];
    const float* cls_W    = (const float*)d_in[7];
    const float* cls_b    = (const float*)d_in[8];

    float* out      = (float*)d_out;
    float* pool_out = out;
    float* att_out  = out + WFEAT;
    float* sen_out  = att_out + (size_t)N * N;
    float* lab_out  = sen_out + (size_t)N * WFEAT;

    static int configured = 0;
    if (!configured) {
        cudaFuncSetAttribute(k3_hmma, cudaFuncAttributeMaxDynamicSharedMemorySize, K3_SMEM);
        configured = 1;
    }

    k1_proj<<<N / 16, 128>>>(inSen, emb, W);
    kf_feat<<<N, 128>>>(a_src, a_dst);
    k2_stats<<<N, 256>>>(adj, selfLink);
    k3_hmma<<<N / 32, 256, K3_SMEM>>>(att_out, sen_out);
    k4_pool_partial<<<64, 128>>>(sen_out);
    k5_head<<<1, 128>>>(cls_W, cls_b, pool_out, lab_out);
}

// round 13
// speedup vs baseline: 1.0388x; 1.0192x over previous
#include <cuda_runtime.h>
#include <cuda_bf16.h>
#include <cstdint>
#include <math.h>

#define N 8192
#define EDIM 128
#define WFEAT 128
#define SLOPE 0.01f
#define NEGINF (-3.0e38f)
#define L2E 1.4426950408889634f

// ---------------- device scratch ----------------
__device__ float g_h[(size_t)N * WFEAT];
__device__ __nv_bfloat16 g_h16_hi[(size_t)N * WFEAT];
__device__ __nv_bfloat16 g_h16_lo[(size_t)N * WFEAT];
__device__ float g_fsrc[N];
__device__ float g_fdst[N];
__device__ float g_rowC[N];
__device__ uint32_t g_mask[(size_t)N * 256];     // packed (adj+self)>0, 8MB
__device__ float g_pmax[256 * WFEAT];            // per-CTA column maxima

// ---------------- helpers ----------------
__device__ __forceinline__ uint32_t smem_u32(const void* p) {
    uint32_t a;
    asm("{ .reg .u64 t; cvta.to.shared.u64 t, %1; cvt.u32.u64 %0, t; }" : "=r"(a) : "l"(p));
    return a;
}
__device__ __forceinline__ uint32_t pack2(float lo, float hi) {
    uint32_t r;
    asm("cvt.rn.bf16x2.f32 %0, %1, %2;" : "=r"(r) : "f"(hi), "f"(lo));
    return r;
}
__device__ __forceinline__ void cp16(uint32_t dst, const void* src) {
    asm volatile("cp.async.cg.shared.global [%0], [%1], 16;" :: "r"(dst), "l"(src));
}
__device__ __forceinline__ void cp_commit() {
    asm volatile("cp.async.commit_group;");
}
__device__ __forceinline__ void cp_wait0() {
    asm volatile("cp.async.wait_group 0;");
}
__device__ __forceinline__ void ldsm_x4(uint32_t* r, uint32_t addr) {
    asm volatile("ldmatrix.sync.aligned.m8n8.x4.shared.b16 {%0,%1,%2,%3}, [%4];"
                 : "=r"(r[0]), "=r"(r[1]), "=r"(r[2]), "=r"(r[3]) : "r"(addr));
}
__device__ __forceinline__ void ldsm_x4_t(uint32_t* r, uint32_t addr) {
    asm volatile("ldmatrix.sync.aligned.m8n8.x4.trans.shared.b16 {%0,%1,%2,%3}, [%4];"
                 : "=r"(r[0]), "=r"(r[1]), "=r"(r[2]), "=r"(r[3]) : "r"(addr));
}
__device__ __forceinline__ void mma16816(float* d, const uint32_t* a, const uint32_t* b) {
    asm volatile(
        "mma.sync.aligned.m16n8k16.row.col.f32.bf16.bf16.f32 "
        "{%0,%1,%2,%3}, {%4,%5,%6,%7}, {%8,%9}, {%0,%1,%2,%3};"
        : "+f"(d[0]), "+f"(d[1]), "+f"(d[2]), "+f"(d[3])
        : "r"(a[0]), "r"(a[1]), "r"(a[2]), "r"(a[3]), "r"(b[0]), "r"(b[1]));
}

// ---------------- K1: h = emb[inSen] @ W (+ bf16 hi/lo + f_src/f_dst) ----------------
__global__ __launch_bounds__(128) void k1_proj(const int* __restrict__ inSen,
                                               const float* __restrict__ emb,
                                               const float* __restrict__ W,
                                               const float* __restrict__ a_src,
                                               const float* __restrict__ a_dst) {
    __shared__ float Ws[64][128];
    __shared__ float wv[16][64];
    __shared__ int   sIdx[16];
    __shared__ float sa[128], sd[128];

    const int tid = threadIdx.x;
    const int i0  = blockIdx.x * 16;

    if (tid < 16) sIdx[tid] = inSen[i0 + tid];
    sa[tid] = a_src[tid];
    sd[tid] = a_dst[tid];
    __syncthreads();

    float acc[16];
#pragma unroll
    for (int r = 0; r < 16; r++) acc[r] = 0.f;

    const int r  = tid >> 3;
    const int p0 = (tid & 7) * 8;

    for (int kc = 0; kc < EDIM; kc += 64) {
#pragma unroll 8
        for (int dd = 0; dd < 64; dd++)
            Ws[dd][tid] = W[(size_t)(kc + dd) * WFEAT + tid];
        {
            const float* er = emb + (size_t)sIdx[r] * EDIM + kc;
#pragma unroll
            for (int p = 0; p < 8; p++) wv[r][p0 + p] = er[p0 + p];
        }
        __syncthreads();
#pragma unroll 16
        for (int dd = 0; dd < 64; dd++) {
            const float w = Ws[dd][tid];
#pragma unroll
            for (int rr = 0; rr < 16; rr++) acc[rr] += wv[rr][dd] * w;
        }
        __syncthreads();
    }
#pragma unroll
    for (int rr = 0; rr < 16; rr++) {
        const float v = acc[rr];
        const size_t idx = (size_t)(i0 + rr) * WFEAT + tid;
        g_h[idx] = v;
        __nv_bfloat16 hb = __float2bfloat16(v);
        g_h16_hi[idx] = hb;
        g_h16_lo[idx] = __float2bfloat16(v - __bfloat162float(hb));
        Ws[rr][tid] = v;                 // stage h tile for f_src/f_dst
    }
    __syncthreads();

    // f_src/f_dst: row rr = tid>>3, 16-col segment per thread, 8-lane reduce
    {
        const int rr  = tid >> 3;
        const int seg = (tid & 7) * 16;
        float ps = 0.f, pd = 0.f;
#pragma unroll
        for (int c2 = 0; c2 < 16; c2++) {
            const float hv = Ws[rr][seg + c2];
            ps += hv * sa[seg + c2];
            pd += hv * sd[seg + c2];
        }
#pragma unroll
        for (int off = 1; off < 8; off <<= 1) {
            ps += __shfl_xor_sync(0xffffffffu, ps, off);
            pd += __shfl_xor_sync(0xffffffffu, pd, off);
        }
        if ((tid & 7) == 0) {
            g_fsrc[i0 + rr] = ps;
            g_fdst[i0 + rr] = pd;
        }
    }
}

// ---------------- K2: row stats + packed mask (front-batched loads) ----------------
__global__ __launch_bounds__(256) void k2_stats(const int* __restrict__ adj,
                                                const int* __restrict__ selfLinkP) {
    const int i   = blockIdx.x;
    const int tid = threadIdx.x;
    const int lane = tid & 31;
    const int selfLink = *selfLinkP;
    const float si = g_fsrc[i];

    const int4* arow = (const int4*)(adj + (size_t)i * N);
    int4 aa[8];
    float4 ff[8];
#pragma unroll
    for (int k = 0; k < 8; k++) aa[k] = __ldg(arow + tid + (k << 8));
#pragma unroll
    for (int k = 0; k < 8; k++) ff[k] = __ldg((const float4*)&g_fdst[(tid + (k << 8)) << 2]);

    float v[32];
    float tm = NEGINF;
#pragma unroll
    for (int k = 0; k < 8; k++) {
        const int idx4 = tid + (k << 8);
        const int j0 = idx4 << 2;
        const int m0 = aa[k].x + ((j0 + 0) == i ? selfLink : 0);
        const int m1 = aa[k].y + ((j0 + 1) == i ? selfLink : 0);
        const int m2 = aa[k].z + ((j0 + 2) == i ? selfLink : 0);
        const int m3 = aa[k].w + ((j0 + 3) == i ? selfLink : 0);

        float x0 = si + ff[k].x, x1 = si + ff[k].y, x2 = si + ff[k].z, x3 = si + ff[k].w;
        x0 = fmaxf(x0, SLOPE * x0);
        x1 = fmaxf(x1, SLOPE * x1);
        x2 = fmaxf(x2, SLOPE * x2);
        x3 = fmaxf(x3, SLOPE * x3);
        const float val0 = (m0 > 0) ? x0 : -1e9f;
        const float val1 = (m1 > 0) ? x1 : -1e9f;
        const float val2 = (m2 > 0) ? x2 : -1e9f;
        const float val3 = (m3 > 0) ? x3 : -1e9f;
        v[(k << 2) + 0] = val0;
        v[(k << 2) + 1] = val1;
        v[(k << 2) + 2] = val2;
        v[(k << 2) + 3] = val3;
        tm = fmaxf(tm, fmaxf(fmaxf(val0, val1), fmaxf(val2, val3)));

        uint32_t wp = ((uint32_t)(m0 > 0) | ((uint32_t)(m1 > 0) << 1) |
                       ((uint32_t)(m2 > 0) << 2) | ((uint32_t)(m3 > 0) << 3))
                      << ((lane & 7) * 4);
        wp |= __shfl_xor_sync(0xffffffffu, wp, 1);
        wp |= __shfl_xor_sync(0xffffffffu, wp, 2);
        wp |= __shfl_xor_sync(0xffffffffu, wp, 4);
        if ((lane & 7) == 0)
            g_mask[(size_t)i * 256 + (idx4 >> 3)] = wp;
    }
    __shared__ float smax[8];
#pragma unroll
    for (int off = 16; off > 0; off >>= 1) tm = fmaxf(tm, __shfl_xor_sync(0xffffffffu, tm, off));
    if ((tid & 31) == 0) smax[tid >> 5] = tm;
    __syncthreads();
    if (tid < 32) {
        float z = (tid < 8) ? smax[tid] : NEGINF;
#pragma unroll
        for (int off = 4; off > 0; off >>= 1) z = fmaxf(z, __shfl_xor_sync(0xffffffffu, z, off));
        if (tid == 0) smax[0] = z;
    }
    __syncthreads();
    const float M = smax[0];

    float ts = 0.f;
#pragma unroll
    for (int k = 0; k < 32; k++) ts += __expf(v[k] - M);
    __shared__ float ssum[8];
#pragma unroll
    for (int off = 16; off > 0; off >>= 1) ts += __shfl_xor_sync(0xffffffffu, ts, off);
    if ((tid & 31) == 0) ssum[tid >> 5] = ts;
    __syncthreads();
    if (tid == 0) {
        float S = 0.f;
#pragma unroll
        for (int w = 0; w < 8; w++) S += ssum[w];
        g_rowC[i] = fmaf(-M, L2E, -__log2f(S));
    }
}

// ---------------- K3: cross-chunk pipelined bitmask attention + HMMA ----------------
// smem (bytes): B hi/lo ring 2 stages [0, 2*34816); A hi/lo double [69632, +2*9216)
#define B_BUF 17408
#define B_STAGE 34816
#define SB_STRIDE 136
#define OFF_A 69632
#define A_BUF 4608
#define A_PAIR 9216
#define SA_STRIDE 72
#define K3_SMEM 88064
#define NCH (N / 64)

// stage-A for chunk cc -> A buffer at aBufOff (+att global write); operands pre-loaded
__device__ __forceinline__ void stage_a(char* smem, uint32_t aBufOff, int cc,
                                        float fs, float Cr,
                                        float* att_row, uint2 mw,
                                        float4 d4a, float4 d4b,
                                        int arow, int acol) {
    const int jbase = cc * 64;
#pragma unroll
    for (int g = 0; g < 2; g++) {
        const int jcol = acol + g * 4;
        const int jg = jbase + jcol;
        const uint32_t w = (jcol & 32) ? mw.y : mw.x;
        const int sh = jcol & 31;
        const float4 d4 = g ? d4b : d4a;

        float v0 = fs + d4.x, v1 = fs + d4.y, v2 = fs + d4.z, v3 = fs + d4.w;
        v0 = fmaxf(v0, SLOPE * v0);
        v1 = fmaxf(v1, SLOPE * v1);
        v2 = fmaxf(v2, SLOPE * v2);
        v3 = fmaxf(v3, SLOPE * v3);
        float r0 = (w & (1u << (sh + 0))) ? fmaf(v0, L2E, Cr) : -1e30f;
        float r1 = (w & (1u << (sh + 1))) ? fmaf(v1, L2E, Cr) : -1e30f;
        float r2 = (w & (1u << (sh + 2))) ? fmaf(v2, L2E, Cr) : -1e30f;
        float r3 = (w & (1u << (sh + 3))) ? fmaf(v3, L2E, Cr) : -1e30f;
        float a0, a1, a2, a3;
        asm("ex2.approx.f32 %0, %1;" : "=f"(a0) : "f"(r0));
        asm("ex2.approx.f32 %0, %1;" : "=f"(a1) : "f"(r1));
        asm("ex2.approx.f32 %0, %1;" : "=f"(a2) : "f"(r2));
        asm("ex2.approx.f32 %0, %1;" : "=f"(a3) : "f"(r3));

        __stcs((float4*)(att_row + jg), make_float4(a0, a1, a2, a3));

        const uint32_t h01 = pack2(a0, a1);
        const uint32_t h23 = pack2(a2, a3);
        const float l0 = a0 - __uint_as_float(h01 << 16);
        const float l1 = a1 - __uint_as_float(h01 & 0xFFFF0000u);
        const float l2 = a2 - __uint_as_float(h23 << 16);
        const float l3 = a3 - __uint_as_float(h23 & 0xFFFF0000u);
        const uint32_t q01 = pack2(l0, l1);
        const uint32_t q23 = pack2(l2, l3);
        const uint32_t ao = (arow * SA_STRIDE + jcol) * 2;
        *(uint2*)(smem + aBufOff + ao)         = make_uint2(h01, h23);
        *(uint2*)(smem + aBufOff + A_BUF + ao) = make_uint2(q01, q23);
    }
}

__global__ __launch_bounds__(256, 2) void k3_hmma(float* __restrict__ att_out,
                                                  float* __restrict__ sen_out) {
    extern __shared__ char smem[];
    const uint32_t sb = smem_u32(smem);

    const int tid = threadIdx.x;
    const int wid = tid >> 5;
    const int lane = tid & 31;
    const int i0 = blockIdx.x * 32;

    // stage-A mapping: 8 threads per row, 8 cols each
    const int arow = tid >> 3;
    const int acol = (tid & 7) * 8;
    const int gi = i0 + arow;
    const float fs = g_fsrc[gi];
    const float Cr = g_rowC[gi];
    float* att_row = att_out + (size_t)gi * N;
    const uint2* mrow = (const uint2*)(g_mask + (size_t)gi * 256);

    // B cp.async mapping
    const int cprowB = tid >> 4;
    const int cpsegB = tid & 15;

    // MMA warp tiling
    const int warp_m = wid >> 2;
    const int warp_n = wid & 3;
    const int lrow = lane & 15;
    const int lgrp = lane >> 4;
    const uint32_t a_lane_off = ((warp_m * 16 + lrow) * SA_STRIDE + lgrp * 8) * 2;
    const uint32_t b_lane_off = (lrow * SB_STRIDE + warp_n * 32 + lgrp * 8) * 2;

    float acc[4][4];
#pragma unroll
    for (int nf = 0; nf < 4; nf++)
#pragma unroll
        for (int q = 0; q < 4; q++) acc[nf][q] = 0.f;

    // ---- prologue: prefetch B(0) into stage 0; stage-A(0) into A buf 0 ----
#pragma unroll
    for (int p = 0; p < 4; p++) {
        const int r = cprowB + p * 16;
        cp16(sb + r * 272 + cpsegB * 16,
             (const char*)g_h16_hi + ((size_t)r * WFEAT + cpsegB * 8) * 2);
        cp16(sb + B_BUF + r * 272 + cpsegB * 16,
             (const char*)g_h16_lo + ((size_t)r * WFEAT + cpsegB * 8) * 2);
    }
    cp_commit();
    {
        const uint2 mw0 = __ldg(&mrow[0]);
        const float4 d4a0 = __ldg((const float4*)&g_fdst[acol]);
        const float4 d4b0 = __ldg((const float4*)&g_fdst[acol + 4]);
        stage_a(smem, OFF_A, 0, fs, Cr, att_row, mw0, d4a0, d4b0, arow, acol);
    }

#pragma unroll 2
    for (int c = 0; c < NCH; c++) {
        const int b = c & 1;

        cp_wait0();        // own share of B(c) landed
        __syncthreads();   // all shares + A[b] visible; MMA(c-1) done -> buffers free

        // --- register-prefetch stage-A(c+1) operands (latency hidden by MMA) ---
        uint2 mw_n = make_uint2(0u, 0u);
        float4 d4a_n = make_float4(0.f, 0.f, 0.f, 0.f);
        float4 d4b_n = d4a_n;
        if (c + 1 < NCH) {
            mw_n  = __ldg(&mrow[c + 1]);
            d4a_n = __ldg((const float4*)&g_fdst[(c + 1) * 64 + acol]);
            d4b_n = __ldg((const float4*)&g_fdst[(c + 1) * 64 + acol + 4]);
        }

        // --- prefetch B(c+1) into stage 1-b (last read by MMA(c-1)) ---
        if (c + 1 < NCH) {
            const int jb = (c + 1) * 64;
            const uint32_t bs = sb + (1 - b) * B_STAGE;
#pragma unroll
            for (int p = 0; p < 4; p++) {
                const int r = cprowB + p * 16;
                cp16(bs + r * 272 + cpsegB * 16,
                     (const char*)g_h16_hi + ((size_t)(jb + r) * WFEAT + cpsegB * 8) * 2);
                cp16(bs + B_BUF + r * 272 + cpsegB * 16,
                     (const char*)g_h16_lo + ((size_t)(jb + r) * WFEAT + cpsegB * 8) * 2);
            }
        }
        cp_commit();

        // --- MMA(c): A from buf b, B from stage b ---
        const uint32_t a_hi = sb + OFF_A + b * A_PAIR + a_lane_off;
        const uint32_t bh_base = sb + b * B_STAGE + b_lane_off;
        const uint32_t bl_base = bh_base + B_BUF;
#pragma unroll
        for (int ks = 0; ks < 4; ks++) {
            uint32_t ah[4], al[4], bh[2][4], bl[2][4];
            {
                const uint32_t aoff = (ks * 16) * 2;
                ldsm_x4(ah, a_hi + aoff);
                ldsm_x4(al, a_hi + A_BUF + aoff);
            }
#pragma unroll
            for (int pr = 0; pr < 2; pr++) {
                const uint32_t boff = (ks * 16 * SB_STRIDE + pr * 16) * 2;
                ldsm_x4_t(bh[pr], bh_base + boff);
                ldsm_x4_t(bl[pr], bl_base + boff);
            }
#pragma unroll
            for (int nf = 0; nf < 4; nf++) {
                const uint32_t* bhp = &bh[nf >> 1][(nf & 1) * 2];
                const uint32_t* blp = &bl[nf >> 1][(nf & 1) * 2];
                mma16816(acc[nf], ah, bhp);
                mma16816(acc[nf], al, bhp);
                mma16816(acc[nf], ah, blp);
            }
        }

        // --- stage-A(c+1) into A buf 1-b (last read by MMA(c-1)) ---
        if (c + 1 < NCH)
            stage_a(smem, OFF_A + (1 - b) * A_PAIR, c + 1, fs, Cr,
                    att_row, mw_n, d4a_n, d4b_n, arow, acol);
    }

    // --- epilogue: sentence tile + fused column-max pooling ---
    const int grp = lane >> 2;
    const int tig = lane & 3;
    float cmax[4][2];
#pragma unroll
    for (int nf = 0; nf < 4; nf++) {
        const int row0 = i0 + warp_m * 16 + grp;
        const int col  = warp_n * 32 + nf * 8 + tig * 2;
        __stcs((float2*)&sen_out[(size_t)row0 * WFEAT + col],
               make_float2(acc[nf][0], acc[nf][1]));
        __stcs((float2*)&sen_out[(size_t)(row0 + 8) * WFEAT + col],
               make_float2(acc[nf][2], acc[nf][3]));
        cmax[nf][0] = fmaxf(acc[nf][0], acc[nf][2]);
        cmax[nf][1] = fmaxf(acc[nf][1], acc[nf][3]);
    }
    // reduce over grp lanes (stride 4,8,16): col-max over this warp's 16 rows
#pragma unroll
    for (int off = 4; off <= 16; off <<= 1)
#pragma unroll
        for (int nf = 0; nf < 4; nf++) {
            cmax[nf][0] = fmaxf(cmax[nf][0], __shfl_xor_sync(0xffffffffu, cmax[nf][0], off));
            cmax[nf][1] = fmaxf(cmax[nf][1], __shfl_xor_sync(0xffffffffu, cmax[nf][1], off));
        }
    __syncthreads();                       // all MMA/loop smem reads done; reuse smem
    float* pm = (float*)smem;              // pm[2][128]
    if (grp == 0) {
#pragma unroll
        for (int nf = 0; nf < 4; nf++) {
            pm[warp_m * 128 + warp_n * 32 + nf * 8 + tig * 2]     = cmax[nf][0];
            pm[warp_m * 128 + warp_n * 32 + nf * 8 + tig * 2 + 1] = cmax[nf][1];
        }
    }
    __syncthreads();
    if (tid < 128)
        g_pmax[blockIdx.x * WFEAT + tid] = fmaxf(pm[tid], pm[128 + tid]);
}

// ---------------- K5: final pool + classifier ----------------
__global__ __launch_bounds__(128) void k5_head(const float* __restrict__ cls_W,
                                               const float* __restrict__ cls_b,
                                               float* __restrict__ pool_out,
                                               float* __restrict__ lab_out) {
    const int c = threadIdx.x;
    __shared__ float pool[WFEAT];
    float m = NEGINF;
#pragma unroll 8
    for (int b = 0; b < 256; b++) m = fmaxf(m, g_pmax[b * WFEAT + c]);
    pool[c] = m;
    pool_out[c] = m;
    __syncthreads();
    if (c == 0) {
        float l0 = cls_b[0], l1 = cls_b[1];
#pragma unroll
        for (int k = 0; k < WFEAT; k++) {
            l0 += pool[k] * cls_W[2 * k];
            l1 += pool[k] * cls_W[2 * k + 1];
        }
        const float mm = fmaxf(l0, l1);
        const float e0 = __expf(l0 - mm), e1 = __expf(l1 - mm);
        const float inv = 1.0f / (e0 + e1);
        lab_out[0] = e0 * inv;
        lab_out[1] = e1 * inv;
    }
}

// ---------------- launch ----------------
extern "C" void kernel_launch(void* const* d_in, const int* in_sizes, int n_in,
                              void* d_out, int out_size) {
    const int*   inSen    = (const int*)d_in[0];
    const int*   adj      = (const int*)d_in[1];
    const int*   selfLink = (const int*)d_in[2];
    const float* emb      = (const float*)d_in[3];
    const float* W        = (const float*)d_in[4];
    const float* a_src    = (const float*)d_in[5];
    const float* a_dst    = (const float*)d_in[6];
    const float* cls_W    = (const float*)d_in[7];
    const float* cls_b    = (const float*)d_in[8];

    float* out      = (float*)d_out;
    float* pool_out = out;
    float* att_out  = out + WFEAT;
    float* sen_out  = att_out + (size_t)N * N;
    float* lab_out  = sen_out + (size_t)N * WFEAT;

    static int configured = 0;
    if (!configured) {
        cudaFuncSetAttribute(k3_hmma, cudaFuncAttributeMaxDynamicSharedMemorySize, K3_SMEM);
        configured = 1;
    }

    k1_proj<<<N / 16, 128>>>(inSen, emb, W, a_src, a_dst);
    k2_stats<<<N, 256>>>(adj, selfLink);
    k3_hmma<<<N / 32, 256, K3_SMEM>>>(att_out, sen_out);
    k5_head<<<1, 128>>>(cls_W, cls_b, pool_out, lab_out);
}

// round 14
// speedup vs baseline: 1.0592x; 1.0196x over previous
#include <cuda_runtime.h>
#include <cuda_bf16.h>
#include <cstdint>
#include <math.h>

#define N 8192
#define EDIM 128
#define WFEAT 128
#define SLOPE 0.01f
#define NEGINF (-3.0e38f)
#define L2E 1.4426950408889634f

// ---------------- device scratch ----------------
__device__ float g_h[(size_t)N * WFEAT];
__device__ __nv_bfloat16 g_h16_hi[(size_t)N * WFEAT];
__device__ __nv_bfloat16 g_h16_lo[(size_t)N * WFEAT];
__device__ float g_fsrc[N];
__device__ float g_fdst[N];
__device__ float g_rowC[N];
__device__ uint32_t g_mask[(size_t)N * 256];     // packed (adj+self)>0, 8MB
__device__ float g_pmax[256 * WFEAT];            // per-CTA column maxima

// ---------------- helpers ----------------
__device__ __forceinline__ uint32_t smem_u32(const void* p) {
    uint32_t a;
    asm("{ .reg .u64 t; cvta.to.shared.u64 t, %1; cvt.u32.u64 %0, t; }" : "=r"(a) : "l"(p));
    return a;
}
__device__ __forceinline__ uint32_t pack2(float lo, float hi) {
    uint32_t r;
    asm("cvt.rn.bf16x2.f32 %0, %1, %2;" : "=r"(r) : "f"(hi), "f"(lo));
    return r;
}
__device__ __forceinline__ void cp16(uint32_t dst, const void* src) {
    asm volatile("cp.async.cg.shared.global [%0], [%1], 16;" :: "r"(dst), "l"(src));
}
__device__ __forceinline__ void cp_commit() {
    asm volatile("cp.async.commit_group;");
}
__device__ __forceinline__ void cp_wait0() {
    asm volatile("cp.async.wait_group 0;");
}
__device__ __forceinline__ void ldsm_x4(uint32_t* r, uint32_t addr) {
    asm volatile("ldmatrix.sync.aligned.m8n8.x4.shared.b16 {%0,%1,%2,%3}, [%4];"
                 : "=r"(r[0]), "=r"(r[1]), "=r"(r[2]), "=r"(r[3]) : "r"(addr));
}
__device__ __forceinline__ void ldsm_x4_t(uint32_t* r, uint32_t addr) {
    asm volatile("ldmatrix.sync.aligned.m8n8.x4.trans.shared.b16 {%0,%1,%2,%3}, [%4];"
                 : "=r"(r[0]), "=r"(r[1]), "=r"(r[2]), "=r"(r[3]) : "r"(addr));
}
__device__ __forceinline__ void mma16816(float* d, const uint32_t* a, const uint32_t* b) {
    asm volatile(
        "mma.sync.aligned.m16n8k16.row.col.f32.bf16.bf16.f32 "
        "{%0,%1,%2,%3}, {%4,%5,%6,%7}, {%8,%9}, {%0,%1,%2,%3};"
        : "+f"(d[0]), "+f"(d[1]), "+f"(d[2]), "+f"(d[3])
        : "r"(a[0]), "r"(a[1]), "r"(a[2]), "r"(a[3]), "r"(b[0]), "r"(b[1]));
}

// ---------------- K1: h = emb[inSen] @ W (+ bf16 hi/lo + f_src/f_dst) ----------------
__global__ __launch_bounds__(128) void k1_proj(const int* __restrict__ inSen,
                                               const float* __restrict__ emb,
                                               const float* __restrict__ W,
                                               const float* __restrict__ a_src,
                                               const float* __restrict__ a_dst) {
    __shared__ float Ws[64][128];
    __shared__ float wv[16][64];
    __shared__ int   sIdx[16];
    __shared__ float sa[128], sd[128];

    const int tid = threadIdx.x;
    const int i0  = blockIdx.x * 16;

    if (tid < 16) sIdx[tid] = inSen[i0 + tid];
    sa[tid] = a_src[tid];
    sd[tid] = a_dst[tid];
    __syncthreads();

    float acc[16];
#pragma unroll
    for (int r = 0; r < 16; r++) acc[r] = 0.f;

    const int r  = tid >> 3;
    const int p0 = (tid & 7) * 8;

    for (int kc = 0; kc < EDIM; kc += 64) {
#pragma unroll 8
        for (int dd = 0; dd < 64; dd++)
            Ws[dd][tid] = W[(size_t)(kc + dd) * WFEAT + tid];
        {
            const float* er = emb + (size_t)sIdx[r] * EDIM + kc;
#pragma unroll
            for (int p = 0; p < 8; p++) wv[r][p0 + p] = er[p0 + p];
        }
        __syncthreads();
#pragma unroll 16
        for (int dd = 0; dd < 64; dd++) {
            const float w = Ws[dd][tid];
#pragma unroll
            for (int rr = 0; rr < 16; rr++) acc[rr] += wv[rr][dd] * w;
        }
        __syncthreads();
    }
#pragma unroll
    for (int rr = 0; rr < 16; rr++) {
        const float v = acc[rr];
        const size_t idx = (size_t)(i0 + rr) * WFEAT + tid;
        g_h[idx] = v;
        __nv_bfloat16 hb = __float2bfloat16(v);
        g_h16_hi[idx] = hb;
        g_h16_lo[idx] = __float2bfloat16(v - __bfloat162float(hb));
        Ws[rr][tid] = v;                 // stage h tile for f_src/f_dst
    }
    __syncthreads();

    // f_src/f_dst: row rr = tid>>3, 16-col segment per thread, 8-lane reduce
    {
        const int rr  = tid >> 3;
        const int seg = (tid & 7) * 16;
        float ps = 0.f, pd = 0.f;
#pragma unroll
        for (int c2 = 0; c2 < 16; c2++) {
            const float hv = Ws[rr][seg + c2];
            ps += hv * sa[seg + c2];
            pd += hv * sd[seg + c2];
        }
#pragma unroll
        for (int off = 1; off < 8; off <<= 1) {
            ps += __shfl_xor_sync(0xffffffffu, ps, off);
            pd += __shfl_xor_sync(0xffffffffu, pd, off);
        }
        if ((tid & 7) == 0) {
            g_fsrc[i0 + rr] = ps;
            g_fdst[i0 + rr] = pd;
        }
    }
}

// ---------------- K2: row stats + packed mask ----------------
__global__ __launch_bounds__(256) void k2_stats(const int* __restrict__ adj,
                                                const int* __restrict__ selfLinkP) {
    const int i   = blockIdx.x;
    const int tid = threadIdx.x;
    const int lane = tid & 31;
    const int selfLink = *selfLinkP;
    const float si = g_fsrc[i];

    const int4* arow = (const int4*)(adj + (size_t)i * N);
    int4 aa[8];
    float4 ff[8];
#pragma unroll
    for (int k = 0; k < 8; k++) aa[k] = __ldg(arow + tid + (k << 8));
#pragma unroll
    for (int k = 0; k < 8; k++) ff[k] = __ldg((const float4*)&g_fdst[(tid + (k << 8)) << 2]);

    float v[32];
    float tm = NEGINF;
#pragma unroll
    for (int k = 0; k < 8; k++) {
        const int idx4 = tid + (k << 8);
        const int j0 = idx4 << 2;
        const int m0 = aa[k].x + ((j0 + 0) == i ? selfLink : 0);
        const int m1 = aa[k].y + ((j0 + 1) == i ? selfLink : 0);
        const int m2 = aa[k].z + ((j0 + 2) == i ? selfLink : 0);
        const int m3 = aa[k].w + ((j0 + 3) == i ? selfLink : 0);

        float x0 = si + ff[k].x, x1 = si + ff[k].y, x2 = si + ff[k].z, x3 = si + ff[k].w;
        x0 = fmaxf(x0, SLOPE * x0);
        x1 = fmaxf(x1, SLOPE * x1);
        x2 = fmaxf(x2, SLOPE * x2);
        x3 = fmaxf(x3, SLOPE * x3);
        const float val0 = (m0 > 0) ? x0 : -1e9f;
        const float val1 = (m1 > 0) ? x1 : -1e9f;
        const float val2 = (m2 > 0) ? x2 : -1e9f;
        const float val3 = (m3 > 0) ? x3 : -1e9f;
        v[(k << 2) + 0] = val0;
        v[(k << 2) + 1] = val1;
        v[(k << 2) + 2] = val2;
        v[(k << 2) + 3] = val3;
        tm = fmaxf(tm, fmaxf(fmaxf(val0, val1), fmaxf(val2, val3)));

        uint32_t wp = ((uint32_t)(m0 > 0) | ((uint32_t)(m1 > 0) << 1) |
                       ((uint32_t)(m2 > 0) << 2) | ((uint32_t)(m3 > 0) << 3))
                      << ((lane & 7) * 4);
        wp |= __shfl_xor_sync(0xffffffffu, wp, 1);
        wp |= __shfl_xor_sync(0xffffffffu, wp, 2);
        wp |= __shfl_xor_sync(0xffffffffu, wp, 4);
        if ((lane & 7) == 0)
            g_mask[(size_t)i * 256 + (idx4 >> 3)] = wp;
    }
    __shared__ float smax[8];
#pragma unroll
    for (int off = 16; off > 0; off >>= 1) tm = fmaxf(tm, __shfl_xor_sync(0xffffffffu, tm, off));
    if ((tid & 31) == 0) smax[tid >> 5] = tm;
    __syncthreads();
    if (tid < 32) {
        float z = (tid < 8) ? smax[tid] : NEGINF;
#pragma unroll
        for (int off = 4; off > 0; off >>= 1) z = fmaxf(z, __shfl_xor_sync(0xffffffffu, z, off));
        if (tid == 0) smax[0] = z;
    }
    __syncthreads();
    const float M = smax[0];

    float ts = 0.f;
#pragma unroll
    for (int k = 0; k < 32; k++) ts += __expf(v[k] - M);
    __shared__ float ssum[8];
#pragma unroll
    for (int off = 16; off > 0; off >>= 1) ts += __shfl_xor_sync(0xffffffffu, ts, off);
    if ((tid & 31) == 0) ssum[tid >> 5] = ts;
    __syncthreads();
    if (tid == 0) {
        float S = 0.f;
#pragma unroll
        for (int w = 0; w < 8; w++) S += ssum[w];
        g_rowC[i] = fmaf(-M, L2E, -__log2f(S));
    }
}

// ---------------- K3: cross-chunk pipelined bitmask attention + HMMA ----------------
// smem (bytes): B hi/lo ring 2 stages [0, 2*34816); A hi/lo double [69632, +2*9216)
#define B_BUF 17408
#define B_STAGE 34816
#define SB_STRIDE 136
#define OFF_A 69632
#define A_BUF 4608
#define A_PAIR 9216
#define SA_STRIDE 72
#define K3_SMEM 88064
#define NCH (N / 64)

// stage-A for chunk cc -> A buffer at aBufOff (+att global write); operands pre-loaded
__device__ __forceinline__ void stage_a(char* smem, uint32_t aBufOff, int cc,
                                        float fs, float Cr,
                                        float* att_row, uint2 mw,
                                        float4 d4a, float4 d4b,
                                        int arow, int acol) {
    const int jbase = cc * 64;
#pragma unroll
    for (int g = 0; g < 2; g++) {
        const int jcol = acol + g * 4;
        const int jg = jbase + jcol;
        const uint32_t w = (jcol & 32) ? mw.y : mw.x;
        const int sh = jcol & 31;
        const float4 d4 = g ? d4b : d4a;

        float v0 = fs + d4.x, v1 = fs + d4.y, v2 = fs + d4.z, v3 = fs + d4.w;
        v0 = fmaxf(v0, SLOPE * v0);
        v1 = fmaxf(v1, SLOPE * v1);
        v2 = fmaxf(v2, SLOPE * v2);
        v3 = fmaxf(v3, SLOPE * v3);
        float r0 = (w & (1u << (sh + 0))) ? fmaf(v0, L2E, Cr) : -1e30f;
        float r1 = (w & (1u << (sh + 1))) ? fmaf(v1, L2E, Cr) : -1e30f;
        float r2 = (w & (1u << (sh + 2))) ? fmaf(v2, L2E, Cr) : -1e30f;
        float r3 = (w & (1u << (sh + 3))) ? fmaf(v3, L2E, Cr) : -1e30f;
        float a0, a1, a2, a3;
        asm("ex2.approx.f32 %0, %1;" : "=f"(a0) : "f"(r0));
        asm("ex2.approx.f32 %0, %1;" : "=f"(a1) : "f"(r1));
        asm("ex2.approx.f32 %0, %1;" : "=f"(a2) : "f"(r2));
        asm("ex2.approx.f32 %0, %1;" : "=f"(a3) : "f"(r3));

        __stcs((float4*)(att_row + jg), make_float4(a0, a1, a2, a3));

        const uint32_t h01 = pack2(a0, a1);
        const uint32_t h23 = pack2(a2, a3);
        const float l0 = a0 - __uint_as_float(h01 << 16);
        const float l1 = a1 - __uint_as_float(h01 & 0xFFFF0000u);
        const float l2 = a2 - __uint_as_float(h23 << 16);
        const float l3 = a3 - __uint_as_float(h23 & 0xFFFF0000u);
        const uint32_t q01 = pack2(l0, l1);
        const uint32_t q23 = pack2(l2, l3);
        const uint32_t ao = (arow * SA_STRIDE + jcol) * 2;
        *(uint2*)(smem + aBufOff + ao)         = make_uint2(h01, h23);
        *(uint2*)(smem + aBufOff + A_BUF + ao) = make_uint2(q01, q23);
    }
}

__global__ __launch_bounds__(256, 2) void k3_hmma(float* __restrict__ att_out,
                                                  float* __restrict__ sen_out) {
    extern __shared__ char smem[];
    const uint32_t sb = smem_u32(smem);

    const int tid = threadIdx.x;
    const int wid = tid >> 5;
    const int lane = tid & 31;
    const int i0 = blockIdx.x * 32;

    // stage-A mapping: 8 threads per row, 8 cols each
    const int arow = tid >> 3;
    const int acol = (tid & 7) * 8;
    const int gi = i0 + arow;
    const float fs = g_fsrc[gi];
    const float Cr = g_rowC[gi];
    float* att_row = att_out + (size_t)gi * N;
    const uint2* mrow = (const uint2*)(g_mask + (size_t)gi * 256);

    // B cp.async mapping
    const int cprowB = tid >> 4;
    const int cpsegB = tid & 15;

    // MMA warp tiling
    const int warp_m = wid >> 2;
    const int warp_n = wid & 3;
    const int lrow = lane & 15;
    const int lgrp = lane >> 4;
    const uint32_t a_lane_off = ((warp_m * 16 + lrow) * SA_STRIDE + lgrp * 8) * 2;
    const uint32_t b_lane_off = (lrow * SB_STRIDE + warp_n * 32 + lgrp * 8) * 2;

    float acc[4][4];
#pragma unroll
    for (int nf = 0; nf < 4; nf++)
#pragma unroll
        for (int q = 0; q < 4; q++) acc[nf][q] = 0.f;

    // ---- prologue: prefetch B(0) into stage 0; stage-A(0) into A buf 0 ----
#pragma unroll
    for (int p = 0; p < 4; p++) {
        const int r = cprowB + p * 16;
        cp16(sb + r * 272 + cpsegB * 16,
             (const char*)g_h16_hi + ((size_t)r * WFEAT + cpsegB * 8) * 2);
        cp16(sb + B_BUF + r * 272 + cpsegB * 16,
             (const char*)g_h16_lo + ((size_t)r * WFEAT + cpsegB * 8) * 2);
    }
    cp_commit();
    {
        const uint2 mw0 = __ldg(&mrow[0]);
        const float4 d4a0 = __ldg((const float4*)&g_fdst[acol]);
        const float4 d4b0 = __ldg((const float4*)&g_fdst[acol + 4]);
        stage_a(smem, OFF_A, 0, fs, Cr, att_row, mw0, d4a0, d4b0, arow, acol);
    }

#pragma unroll 2
    for (int c = 0; c < NCH; c++) {
        const int b = c & 1;

        cp_wait0();        // own share of B(c) landed
        __syncthreads();   // all shares + A[b] visible; MMA(c-1) done -> buffers free

        // --- register-prefetch stage-A(c+1) operands (latency hidden by MMA) ---
        uint2 mw_n = make_uint2(0u, 0u);
        float4 d4a_n = make_float4(0.f, 0.f, 0.f, 0.f);
        float4 d4b_n = d4a_n;
        if (c + 1 < NCH) {
            mw_n  = __ldg(&mrow[c + 1]);
            d4a_n = __ldg((const float4*)&g_fdst[(c + 1) * 64 + acol]);
            d4b_n = __ldg((const float4*)&g_fdst[(c + 1) * 64 + acol + 4]);
        }

        // --- prefetch B(c+1) into stage 1-b (last read by MMA(c-1)) ---
        if (c + 1 < NCH) {
            const int jb = (c + 1) * 64;
            const uint32_t bs = sb + (1 - b) * B_STAGE;
#pragma unroll
            for (int p = 0; p < 4; p++) {
                const int r = cprowB + p * 16;
                cp16(bs + r * 272 + cpsegB * 16,
                     (const char*)g_h16_hi + ((size_t)(jb + r) * WFEAT + cpsegB * 8) * 2);
                cp16(bs + B_BUF + r * 272 + cpsegB * 16,
                     (const char*)g_h16_lo + ((size_t)(jb + r) * WFEAT + cpsegB * 8) * 2);
            }
        }
        cp_commit();

        // --- MMA(c): A from buf b, B from stage b ---
        const uint32_t a_hi = sb + OFF_A + b * A_PAIR + a_lane_off;
        const uint32_t bh_base = sb + b * B_STAGE + b_lane_off;
        const uint32_t bl_base = bh_base + B_BUF;
#pragma unroll
        for (int ks = 0; ks < 4; ks++) {
            uint32_t ah[4], al[4], bh[2][4], bl[2][4];
            {
                const uint32_t aoff = (ks * 16) * 2;
                ldsm_x4(ah, a_hi + aoff);
                ldsm_x4(al, a_hi + A_BUF + aoff);
            }
#pragma unroll
            for (int pr = 0; pr < 2; pr++) {
                const uint32_t boff = (ks * 16 * SB_STRIDE + pr * 16) * 2;
                ldsm_x4_t(bh[pr], bh_base + boff);
                ldsm_x4_t(bl[pr], bl_base + boff);
            }
#pragma unroll
            for (int nf = 0; nf < 4; nf++) {
                const uint32_t* bhp = &bh[nf >> 1][(nf & 1) * 2];
                const uint32_t* blp = &bl[nf >> 1][(nf & 1) * 2];
                mma16816(acc[nf], ah, bhp);
                mma16816(acc[nf], al, bhp);
                mma16816(acc[nf], ah, blp);
            }
        }

        // --- stage-A(c+1) into A buf 1-b (last read by MMA(c-1)) ---
        if (c + 1 < NCH)
            stage_a(smem, OFF_A + (1 - b) * A_PAIR, c + 1, fs, Cr,
                    att_row, mw_n, d4a_n, d4b_n, arow, acol);
    }

    // --- epilogue: sentence tile + fused column-max pooling ---
    const int grp = lane >> 2;
    const int tig = lane & 3;
    float cmax[4][2];
#pragma unroll
    for (int nf = 0; nf < 4; nf++) {
        const int row0 = i0 + warp_m * 16 + grp;
        const int col  = warp_n * 32 + nf * 8 + tig * 2;
        __stcs((float2*)&sen_out[(size_t)row0 * WFEAT + col],
               make_float2(acc[nf][0], acc[nf][1]));
        __stcs((float2*)&sen_out[(size_t)(row0 + 8) * WFEAT + col],
               make_float2(acc[nf][2], acc[nf][3]));
        cmax[nf][0] = fmaxf(acc[nf][0], acc[nf][2]);
        cmax[nf][1] = fmaxf(acc[nf][1], acc[nf][3]);
    }
#pragma unroll
    for (int off = 4; off <= 16; off <<= 1)
#pragma unroll
        for (int nf = 0; nf < 4; nf++) {
            cmax[nf][0] = fmaxf(cmax[nf][0], __shfl_xor_sync(0xffffffffu, cmax[nf][0], off));
            cmax[nf][1] = fmaxf(cmax[nf][1], __shfl_xor_sync(0xffffffffu, cmax[nf][1], off));
        }
    __syncthreads();
    float* pm = (float*)smem;              // pm[2][128]
    if (grp == 0) {
#pragma unroll
        for (int nf = 0; nf < 4; nf++) {
            pm[warp_m * 128 + warp_n * 32 + nf * 8 + tig * 2]     = cmax[nf][0];
            pm[warp_m * 128 + warp_n * 32 + nf * 8 + tig * 2 + 1] = cmax[nf][1];
        }
    }
    __syncthreads();
    if (tid < 128)
        g_pmax[blockIdx.x * WFEAT + tid] = fmaxf(pm[tid], pm[128 + tid]);
}

// ---------------- K5: final pool + classifier (parallelized reduce) ----------------
__global__ __launch_bounds__(1024) void k5_head(const float* __restrict__ cls_W,
                                                const float* __restrict__ cls_b,
                                                float* __restrict__ pool_out,
                                                float* __restrict__ lab_out) {
    const int tid  = threadIdx.x;
    const int col  = tid & 127;
    const int part = tid >> 7;              // 0..7
    __shared__ float pp[8][WFEAT];
    __shared__ float pool[WFEAT];

    float m = NEGINF;
    const int b0 = part * 32;
#pragma unroll 8
    for (int b = 0; b < 32; b++)
        m = fmaxf(m, __ldg(&g_pmax[(b0 + b) * WFEAT + col]));
    pp[part][col] = m;
    __syncthreads();

    if (tid < 128) {
        float mm = pp[0][tid];
#pragma unroll
        for (int p = 1; p < 8; p++) mm = fmaxf(mm, pp[p][tid]);
        pool[tid] = mm;
        pool_out[tid] = mm;
    }
    __syncthreads();

    if (tid < 32) {
        // parallel 128-dot across 32 lanes, 4 elements each
        float l0 = 0.f, l1 = 0.f;
#pragma unroll
        for (int q = 0; q < 4; q++) {
            const int k = tid * 4 + q;
            const float pv = pool[k];
            l0 += pv * __ldg(&cls_W[2 * k]);
            l1 += pv * __ldg(&cls_W[2 * k + 1]);
        }
#pragma unroll
        for (int off = 16; off > 0; off >>= 1) {
            l0 += __shfl_xor_sync(0xffffffffu, l0, off);
            l1 += __shfl_xor_sync(0xffffffffu, l1, off);
        }
        if (tid == 0) {
            l0 += __ldg(&cls_b[0]);
            l1 += __ldg(&cls_b[1]);
            const float mm = fmaxf(l0, l1);
            const float e0 = __expf(l0 - mm), e1 = __expf(l1 - mm);
            const float inv = 1.0f / (e0 + e1);
            lab_out[0] = e0 * inv;
            lab_out[1] = e1 * inv;
        }
    }
}

// ---------------- launch ----------------
extern "C" void kernel_launch(void* const* d_in, const int* in_sizes, int n_in,
                              void* d_out, int out_size) {
    const int*   inSen    = (const int*)d_in[0];
    const int*   adj      = (const int*)d_in[1];
    const int*   selfLink = (const int*)d_in[2];
    const float* emb      = (const float*)d_in[3];
    const float* W        = (const float*)d_in[4];
    const float* a_src    = (const float*)d_in[5];
    const float* a_dst    = (const float*)d_in[6];
    const float* cls_W    = (const float*)d_in[7];
    const float* cls_b    = (const float*)d_in[8];

    float* out      = (float*)d_out;
    float* pool_out = out;
    float* att_out  = out + WFEAT;
    float* sen_out  = att_out + (size_t)N * N;
    float* lab_out  = sen_out + (size_t)N * WFEAT;

    static int configured = 0;
    if (!configured) {
        cudaFuncSetAttribute(k3_hmma, cudaFuncAttributeMaxDynamicSharedMemorySize, K3_SMEM);
        configured = 1;
    }

    k1_proj<<<N / 16, 128>>>(inSen, emb, W, a_src, a_dst);
    k2_stats<<<N, 256>>>(adj, selfLink);
    k3_hmma<<<N / 32, 256, K3_SMEM>>>(att_out, sen_out);
    k5_head<<<1, 1024>>>(cls_W, cls_b, pool_out, lab_out);
}

// round 15
// speedup vs baseline: 1.3730x; 1.2963x over previous
#include <cuda_runtime.h>
#include <cuda_bf16.h>
#include <cuda_fp16.h>
#include <cstdint>
#include <math.h>

#define N 8192
#define EDIM 128
#define WFEAT 128
#define SLOPE 0.01f
#define NEGINF (-3.0e38f)
#define L2E 1.4426950408889634f

// ---------------- device scratch ----------------
__device__ __half g_h16[(size_t)N * WFEAT];      // h in fp16 (B operand)
__device__ float g_fsrc[N];
__device__ float g_fdst[N];
__device__ float g_rowC[N];
__device__ uint32_t g_mask[(size_t)N * 256];     // packed (adj+self)>0, 8MB
__device__ float g_pmax[256 * WFEAT];            // per-CTA column maxima

// ---------------- helpers ----------------
__device__ __forceinline__ uint32_t smem_u32(const void* p) {
    uint32_t a;
    asm("{ .reg .u64 t; cvta.to.shared.u64 t, %1; cvt.u32.u64 %0, t; }" : "=r"(a) : "l"(p));
    return a;
}
__device__ __forceinline__ void cp16(uint32_t dst, const void* src) {
    asm volatile("cp.async.cg.shared.global [%0], [%1], 16;" :: "r"(dst), "l"(src));
}
__device__ __forceinline__ void cp_commit() {
    asm volatile("cp.async.commit_group;");
}
__device__ __forceinline__ void cp_wait0() {
    asm volatile("cp.async.wait_group 0;");
}
__device__ __forceinline__ void ldsm_x4(uint32_t* r, uint32_t addr) {
    asm volatile("ldmatrix.sync.aligned.m8n8.x4.shared.b16 {%0,%1,%2,%3}, [%4];"
                 : "=r"(r[0]), "=r"(r[1]), "=r"(r[2]), "=r"(r[3]) : "r"(addr));
}
__device__ __forceinline__ void ldsm_x4_t(uint32_t* r, uint32_t addr) {
    asm volatile("ldmatrix.sync.aligned.m8n8.x4.trans.shared.b16 {%0,%1,%2,%3}, [%4];"
                 : "=r"(r[0]), "=r"(r[1]), "=r"(r[2]), "=r"(r[3]) : "r"(addr));
}
__device__ __forceinline__ void mma_f16(float* d, const uint32_t* a, const uint32_t* b) {
    asm volatile(
        "mma.sync.aligned.m16n8k16.row.col.f32.f16.f16.f32 "
        "{%0,%1,%2,%3}, {%4,%5,%6,%7}, {%8,%9}, {%0,%1,%2,%3};"
        : "+f"(d[0]), "+f"(d[1]), "+f"(d[2]), "+f"(d[3])
        : "r"(a[0]), "r"(a[1]), "r"(a[2]), "r"(a[3]), "r"(b[0]), "r"(b[1]));
}

// ---------------- K1: h = emb[inSen] @ W (fp16 h + f_src/f_dst) ----------------
__global__ __launch_bounds__(128) void k1_proj(const int* __restrict__ inSen,
                                               const float* __restrict__ emb,
                                               const float* __restrict__ W,
                                               const float* __restrict__ a_src,
                                               const float* __restrict__ a_dst) {
    __shared__ float Ws[64][128];
    __shared__ float wv[16][64];
    __shared__ int   sIdx[16];
    __shared__ float sa[128], sd[128];

    const int tid = threadIdx.x;
    const int i0  = blockIdx.x * 16;

    if (tid < 16) sIdx[tid] = inSen[i0 + tid];
    sa[tid] = a_src[tid];
    sd[tid] = a_dst[tid];
    __syncthreads();

    float acc[16];
#pragma unroll
    for (int r = 0; r < 16; r++) acc[r] = 0.f;

    const int r  = tid >> 3;
    const int p0 = (tid & 7) * 8;

    for (int kc = 0; kc < EDIM; kc += 64) {
#pragma unroll 8
        for (int dd = 0; dd < 64; dd++)
            Ws[dd][tid] = W[(size_t)(kc + dd) * WFEAT + tid];
        {
            const float* er = emb + (size_t)sIdx[r] * EDIM + kc;
#pragma unroll
            for (int p = 0; p < 8; p++) wv[r][p0 + p] = er[p0 + p];
        }
        __syncthreads();
#pragma unroll 16
        for (int dd = 0; dd < 64; dd++) {
            const float w = Ws[dd][tid];
#pragma unroll
            for (int rr = 0; rr < 16; rr++) acc[rr] += wv[rr][dd] * w;
        }
        __syncthreads();
    }
#pragma unroll
    for (int rr = 0; rr < 16; rr++) {
        const float v = acc[rr];
        g_h16[(size_t)(i0 + rr) * WFEAT + tid] = __float2half(v);
        Ws[rr][tid] = v;                 // stage h tile for f_src/f_dst
    }
    __syncthreads();

    // f_src/f_dst: row rr = tid>>3, 16-col segment per thread, 8-lane reduce
    {
        const int rr  = tid >> 3;
        const int seg = (tid & 7) * 16;
        float ps = 0.f, pd = 0.f;
#pragma unroll
        for (int c2 = 0; c2 < 16; c2++) {
            const float hv = Ws[rr][seg + c2];
            ps += hv * sa[seg + c2];
            pd += hv * sd[seg + c2];
        }
#pragma unroll
        for (int off = 1; off < 8; off <<= 1) {
            ps += __shfl_xor_sync(0xffffffffu, ps, off);
            pd += __shfl_xor_sync(0xffffffffu, pd, off);
        }
        if ((tid & 7) == 0) {
            g_fsrc[i0 + rr] = ps;
            g_fdst[i0 + rr] = pd;
        }
    }
}

// ---------------- K2: row stats + packed mask ----------------
__global__ __launch_bounds__(256) void k2_stats(const int* __restrict__ adj,
                                                const int* __restrict__ selfLinkP) {
    const int i   = blockIdx.x;
    const int tid = threadIdx.x;
    const int lane = tid & 31;
    const int selfLink = *selfLinkP;
    const float si = g_fsrc[i];

    const int4* arow = (const int4*)(adj + (size_t)i * N);
    int4 aa[8];
    float4 ff[8];
#pragma unroll
    for (int k = 0; k < 8; k++) aa[k] = __ldg(arow + tid + (k << 8));
#pragma unroll
    for (int k = 0; k < 8; k++) ff[k] = __ldg((const float4*)&g_fdst[(tid + (k << 8)) << 2]);

    float tm = NEGINF;
#pragma unroll
    for (int k = 0; k < 8; k++) {
        const int idx4 = tid + (k << 8);
        const int j0 = idx4 << 2;
        const int m0 = aa[k].x + ((j0 + 0) == i ? selfLink : 0);
        const int m1 = aa[k].y + ((j0 + 1) == i ? selfLink : 0);
        const int m2 = aa[k].z + ((j0 + 2) == i ? selfLink : 0);
        const int m3 = aa[k].w + ((j0 + 3) == i ? selfLink : 0);

        float x0 = si + ff[k].x, x1 = si + ff[k].y, x2 = si + ff[k].z, x3 = si + ff[k].w;
        x0 = fmaxf(x0, SLOPE * x0);
        x1 = fmaxf(x1, SLOPE * x1);
        x2 = fmaxf(x2, SLOPE * x2);
        x3 = fmaxf(x3, SLOPE * x3);
        const float val0 = (m0 > 0) ? x0 : -1e9f;
        const float val1 = (m1 > 0) ? x1 : -1e9f;
        const float val2 = (m2 > 0) ? x2 : -1e9f;
        const float val3 = (m3 > 0) ? x3 : -1e9f;
        tm = fmaxf(tm, fmaxf(fmaxf(val0, val1), fmaxf(val2, val3)));

        uint32_t wp = ((uint32_t)(m0 > 0) | ((uint32_t)(m1 > 0) << 1) |
                       ((uint32_t)(m2 > 0) << 2) | ((uint32_t)(m3 > 0) << 3))
                      << ((lane & 7) * 4);
        wp |= __shfl_xor_sync(0xffffffffu, wp, 1);
        wp |= __shfl_xor_sync(0xffffffffu, wp, 2);
        wp |= __shfl_xor_sync(0xffffffffu, wp, 4);
        if ((lane & 7) == 0)
            g_mask[(size_t)i * 256 + (idx4 >> 3)] = wp;
    }
    __shared__ float smax[8];
#pragma unroll
    for (int off = 16; off > 0; off >>= 1) tm = fmaxf(tm, __shfl_xor_sync(0xffffffffu, tm, off));
    if ((tid & 31) == 0) smax[tid >> 5] = tm;
    __syncthreads();
    if (tid < 32) {
        float z = (tid < 8) ? smax[tid] : NEGINF;
#pragma unroll
        for (int off = 4; off > 0; off >>= 1) z = fmaxf(z, __shfl_xor_sync(0xffffffffu, z, off));
        if (tid == 0) smax[0] = z;
    }
    __syncthreads();
    const float M = smax[0];

    // second pass: recompute masked values from live aa/ff registers
    float ts = 0.f;
#pragma unroll
    for (int k = 0; k < 8; k++) {
        const int j0 = (tid + (k << 8)) << 2;
        const int m0 = aa[k].x + ((j0 + 0) == i ? selfLink : 0);
        const int m1 = aa[k].y + ((j0 + 1) == i ? selfLink : 0);
        const int m2 = aa[k].z + ((j0 + 2) == i ? selfLink : 0);
        const int m3 = aa[k].w + ((j0 + 3) == i ? selfLink : 0);
        float x0 = si + ff[k].x, x1 = si + ff[k].y, x2 = si + ff[k].z, x3 = si + ff[k].w;
        x0 = fmaxf(x0, SLOPE * x0);
        x1 = fmaxf(x1, SLOPE * x1);
        x2 = fmaxf(x2, SLOPE * x2);
        x3 = fmaxf(x3, SLOPE * x3);
        ts += __expf(((m0 > 0) ? x0 : -1e9f) - M);
        ts += __expf(((m1 > 0) ? x1 : -1e9f) - M);
        ts += __expf(((m2 > 0) ? x2 : -1e9f) - M);
        ts += __expf(((m3 > 0) ? x3 : -1e9f) - M);
    }
    __shared__ float ssum[8];
#pragma unroll
    for (int off = 16; off > 0; off >>= 1) ts += __shfl_xor_sync(0xffffffffu, ts, off);
    if ((tid & 31) == 0) ssum[tid >> 5] = ts;
    __syncthreads();
    if (tid == 0) {
        float S = 0.f;
#pragma unroll
        for (int w = 0; w < 8; w++) S += ssum[w];
        g_rowC[i] = fmaf(-M, L2E, -__log2f(S));
    }
}

// ---------------- K3: fp16 2-term pipelined bitmask attention + HMMA ----------------
// smem (bytes): B ring 2 stages [0, 2*17408); A hi/lo double [34816, +2*9216)
#define B_BUF 17408
#define SB_STRIDE 136
#define OFF_A 34816
#define A_BUF 4608
#define A_PAIR 9216
#define SA_STRIDE 72
#define K3_SMEM 53248
#define NCH (N / 64)

// stage-A for chunk cc -> A fp16 hi/lo buffers (+att global write); operands pre-loaded
__device__ __forceinline__ void stage_a(char* smem, uint32_t aBufOff, int cc,
                                        float fs, float Cr,
                                        float* att_row, uint2 mw,
                                        float4 d4a, float4 d4b,
                                        int arow, int acol) {
    const int jbase = cc * 64;
#pragma unroll
    for (int g = 0; g < 2; g++) {
        const int jcol = acol + g * 4;
        const int jg = jbase + jcol;
        const uint32_t w = (jcol & 32) ? mw.y : mw.x;
        const int sh = jcol & 31;
        const float4 d4 = g ? d4b : d4a;

        float v0 = fs + d4.x, v1 = fs + d4.y, v2 = fs + d4.z, v3 = fs + d4.w;
        v0 = fmaxf(v0, SLOPE * v0);
        v1 = fmaxf(v1, SLOPE * v1);
        v2 = fmaxf(v2, SLOPE * v2);
        v3 = fmaxf(v3, SLOPE * v3);
        float r0 = (w & (1u << (sh + 0))) ? fmaf(v0, L2E, Cr) : -1e30f;
        float r1 = (w & (1u << (sh + 1))) ? fmaf(v1, L2E, Cr) : -1e30f;
        float r2 = (w & (1u << (sh + 2))) ? fmaf(v2, L2E, Cr) : -1e30f;
        float r3 = (w & (1u << (sh + 3))) ? fmaf(v3, L2E, Cr) : -1e30f;
        float a0, a1, a2, a3;
        asm("ex2.approx.f32 %0, %1;" : "=f"(a0) : "f"(r0));
        asm("ex2.approx.f32 %0, %1;" : "=f"(a1) : "f"(r1));
        asm("ex2.approx.f32 %0, %1;" : "=f"(a2) : "f"(r2));
        asm("ex2.approx.f32 %0, %1;" : "=f"(a3) : "f"(r3));

        __stcs((float4*)(att_row + jg), make_float4(a0, a1, a2, a3));

        // fp16 hi/lo split of attention values
        __half2 p01 = __floats2half2_rn(a0, a1);
        __half2 p23 = __floats2half2_rn(a2, a3);
        const float l0 = a0 - __low2float(p01);
        const float l1 = a1 - __high2float(p01);
        const float l2 = a2 - __low2float(p23);
        const float l3 = a3 - __high2float(p23);
        __half2 q01 = __floats2half2_rn(l0, l1);
        __half2 q23 = __floats2half2_rn(l2, l3);
        const uint32_t ao = (arow * SA_STRIDE + jcol) * 2;
        *(uint2*)(smem + aBufOff + ao) =
            make_uint2(*(uint32_t*)&p01, *(uint32_t*)&p23);
        *(uint2*)(smem + aBufOff + A_BUF + ao) =
            make_uint2(*(uint32_t*)&q01, *(uint32_t*)&q23);
    }
}

__global__ __launch_bounds__(256, 2) void k3_hmma(float* __restrict__ att_out,
                                                  float* __restrict__ sen_out) {
    extern __shared__ char smem[];
    const uint32_t sb = smem_u32(smem);

    const int tid = threadIdx.x;
    const int wid = tid >> 5;
    const int lane = tid & 31;
    const int i0 = blockIdx.x * 32;

    // stage-A mapping: 8 threads per row, 8 cols each
    const int arow = tid >> 3;
    const int acol = (tid & 7) * 8;
    const int gi = i0 + arow;
    const float fs = g_fsrc[gi];
    const float Cr = g_rowC[gi];
    float* att_row = att_out + (size_t)gi * N;
    const uint2* mrow = (const uint2*)(g_mask + (size_t)gi * 256);

    // B cp.async mapping
    const int cprowB = tid >> 4;
    const int cpsegB = tid & 15;

    // MMA warp tiling
    const int warp_m = wid >> 2;
    const int warp_n = wid & 3;
    const int lrow = lane & 15;
    const int lgrp = lane >> 4;
    const uint32_t a_lane_off = ((warp_m * 16 + lrow) * SA_STRIDE + lgrp * 8) * 2;
    const uint32_t b_lane_off = (lrow * SB_STRIDE + warp_n * 32 + lgrp * 8) * 2;

    float acc[4][4];
#pragma unroll
    for (int nf = 0; nf < 4; nf++)
#pragma unroll
        for (int q = 0; q < 4; q++) acc[nf][q] = 0.f;

    // ---- prologue: prefetch B(0) into stage 0; stage-A(0) into A buf 0 ----
#pragma unroll
    for (int p = 0; p < 4; p++) {
        const int r = cprowB + p * 16;
        cp16(sb + r * 272 + cpsegB * 16,
             (const char*)g_h16 + ((size_t)r * WFEAT + cpsegB * 8) * 2);
    }
    cp_commit();
    {
        const uint2 mw0 = __ldg(&mrow[0]);
        const float4 d4a0 = __ldg((const float4*)&g_fdst[acol]);
        const float4 d4b0 = __ldg((const float4*)&g_fdst[acol + 4]);
        stage_a(smem, OFF_A, 0, fs, Cr, att_row, mw0, d4a0, d4b0, arow, acol);
    }

#pragma unroll 2
    for (int c = 0; c < NCH; c++) {
        const int b = c & 1;

        cp_wait0();        // own share of B(c) landed
        __syncthreads();   // all shares + A[b] visible; MMA(c-1) done -> buffers free

        // --- register-prefetch stage-A(c+1) operands (latency hidden by MMA) ---
        uint2 mw_n = make_uint2(0u, 0u);
        float4 d4a_n = make_float4(0.f, 0.f, 0.f, 0.f);
        float4 d4b_n = d4a_n;
        if (c + 1 < NCH) {
            mw_n  = __ldg(&mrow[c + 1]);
            d4a_n = __ldg((const float4*)&g_fdst[(c + 1) * 64 + acol]);
            d4b_n = __ldg((const float4*)&g_fdst[(c + 1) * 64 + acol + 4]);
        }

        // --- prefetch B(c+1) into stage 1-b (last read by MMA(c-1)) ---
        if (c + 1 < NCH) {
            const int jb = (c + 1) * 64;
            const uint32_t bs = sb + (1 - b) * B_BUF;
#pragma unroll
            for (int p = 0; p < 4; p++) {
                const int r = cprowB + p * 16;
                cp16(bs + r * 272 + cpsegB * 16,
                     (const char*)g_h16 + ((size_t)(jb + r) * WFEAT + cpsegB * 8) * 2);
            }
        }
        cp_commit();

        // --- MMA(c): A hi/lo from buf b, B from stage b ---
        const uint32_t a_hi = sb + OFF_A + b * A_PAIR + a_lane_off;
        const uint32_t bh_base = sb + b * B_BUF + b_lane_off;
#pragma unroll
        for (int ks = 0; ks < 4; ks++) {
            uint32_t ah[4], al[4], bh[2][4];
            {
                const uint32_t aoff = (ks * 16) * 2;
                ldsm_x4(ah, a_hi + aoff);
                ldsm_x4(al, a_hi + A_BUF + aoff);
            }
#pragma unroll
            for (int pr = 0; pr < 2; pr++) {
                const uint32_t boff = (ks * 16 * SB_STRIDE + pr * 16) * 2;
                ldsm_x4_t(bh[pr], bh_base + boff);
            }
#pragma unroll
            for (int nf = 0; nf < 4; nf++) {
                const uint32_t* bhp = &bh[nf >> 1][(nf & 1) * 2];
                mma_f16(acc[nf], ah, bhp);
                mma_f16(acc[nf], al, bhp);
            }
        }

        // --- stage-A(c+1) into A buf 1-b (last read by MMA(c-1)) ---
        if (c + 1 < NCH)
            stage_a(smem, OFF_A + (1 - b) * A_PAIR, c + 1, fs, Cr,
                    att_row, mw_n, d4a_n, d4b_n, arow, acol);
    }

    // --- epilogue: sentence tile + fused column-max pooling ---
    const int grp = lane >> 2;
    const int tig = lane & 3;
    float cmax[4][2];
#pragma unroll
    for (int nf = 0; nf < 4; nf++) {
        const int row0 = i0 + warp_m * 16 + grp;
        const int col  = warp_n * 32 + nf * 8 + tig * 2;
        __stcs((float2*)&sen_out[(size_t)row0 * WFEAT + col],
               make_float2(acc[nf][0], acc[nf][1]));
        __stcs((float2*)&sen_out[(size_t)(row0 + 8) * WFEAT + col],
               make_float2(acc[nf][2], acc[nf][3]));
        cmax[nf][0] = fmaxf(acc[nf][0], acc[nf][2]);
        cmax[nf][1] = fmaxf(acc[nf][1], acc[nf][3]);
    }
#pragma unroll
    for (int off = 4; off <= 16; off <<= 1)
#pragma unroll
        for (int nf = 0; nf < 4; nf++) {
            cmax[nf][0] = fmaxf(cmax[nf][0], __shfl_xor_sync(0xffffffffu, cmax[nf][0], off));
            cmax[nf][1] = fmaxf(cmax[nf][1], __shfl_xor_sync(0xffffffffu, cmax[nf][1], off));
        }
    __syncthreads();
    float* pm = (float*)smem;              // pm[2][128]
    if (grp == 0) {
#pragma unroll
        for (int nf = 0; nf < 4; nf++) {
            pm[warp_m * 128 + warp_n * 32 + nf * 8 + tig * 2]     = cmax[nf][0];
            pm[warp_m * 128 + warp_n * 32 + nf * 8 + tig * 2 + 1] = cmax[nf][1];
        }
    }
    __syncthreads();
    if (tid < 128)
        g_pmax[blockIdx.x * WFEAT + tid] = fmaxf(pm[tid], pm[128 + tid]);
}

// ---------------- K5: final pool + classifier (parallelized reduce) ----------------
__global__ __launch_bounds__(1024) void k5_head(const float* __restrict__ cls_W,
                                                const float* __restrict__ cls_b,
                                                float* __restrict__ pool_out,
                                                float* __restrict__ lab_out) {
    const int tid  = threadIdx.x;
    const int col  = tid & 127;
    const int part = tid >> 7;              // 0..7
    __shared__ float pp[8][WFEAT];
    __shared__ float pool[WFEAT];

    float m = NEGINF;
    const int b0 = part * 32;
#pragma unroll 8
    for (int b = 0; b < 32; b++)
        m = fmaxf(m, __ldg(&g_pmax[(b0 + b) * WFEAT + col]));
    pp[part][col] = m;
    __syncthreads();

    if (tid < 128) {
        float mm = pp[0][tid];
#pragma unroll
        for (int p = 1; p < 8; p++) mm = fmaxf(mm, pp[p][tid]);
        pool[tid] = mm;
        pool_out[tid] = mm;
    }
    __syncthreads();

    if (tid < 32) {
        float l0 = 0.f, l1 = 0.f;
#pragma unroll
        for (int q = 0; q < 4; q++) {
            const int k = tid * 4 + q;
            const float pv = pool[k];
            l0 += pv * __ldg(&cls_W[2 * k]);
            l1 += pv * __ldg(&cls_W[2 * k + 1]);
        }
#pragma unroll
        for (int off = 16; off > 0; off >>= 1) {
            l0 += __shfl_xor_sync(0xffffffffu, l0, off);
            l1 += __shfl_xor_sync(0xffffffffu, l1, off);
        }
        if (tid == 0) {
            l0 += __ldg(&cls_b[0]);
            l1 += __ldg(&cls_b[1]);
            const float mm = fmaxf(l0, l1);
            const float e0 = __expf(l0 - mm), e1 = __expf(l1 - mm);
            const float inv = 1.0f / (e0 + e1);
            lab_out[0] = e0 * inv;
            lab_out[1] = e1 * inv;
        }
    }
}

// ---------------- launch ----------------
extern "C" void kernel_launch(void* const* d_in, const int* in_sizes, int n_in,
                              void* d_out, int out_size) {
    const int*   inSen    = (const int*)d_in[0];
    const int*   adj      = (const int*)d_in[1];
    const int*   selfLink = (const int*)d_in[2];
    const float* emb      = (const float*)d_in[3];
    const float* W        = (const float*)d_in[4];
    const float* a_src    = (const float*)d_in[5];
    const float* a_dst    = (const float*)d_in[6];
    const float* cls_W    = (const float*)d_in[7];
    const float* cls_b    = (const float*)d_in[8];

    float* out      = (float*)d_out;
    float* pool_out = out;
    float* att_out  = out + WFEAT;
    float* sen_out  = att_out + (size_t)N * N;
    float* lab_out  = sen_out + (size_t)N * WFEAT;

    static int configured = 0;
    if (!configured) {
        cudaFuncSetAttribute(k3_hmma, cudaFuncAttributeMaxDynamicSharedMemorySize, K3_SMEM);
        configured = 1;
    }

    k1_proj<<<N / 16, 128>>>(inSen, emb, W, a_src, a_dst);
    k2_stats<<<N, 256>>>(adj, selfLink);
    k3_hmma<<<N / 32, 256, K3_SMEM>>>(att_out, sen_out);
    k5_head<<<1, 1024>>>(cls_W, cls_b, pool_out, lab_out);
}

// round 16
// speedup vs baseline: 1.4358x; 1.0457x over previous
#include <cuda_runtime.h>
#include <cuda_bf16.h>
#include <cuda_fp16.h>
#include <cstdint>
#include <math.h>

#define N 8192
#define EDIM 128
#define WFEAT 128
#define SLOPE 0.01f
#define NEGINF (-3.0e38f)
#define L2E 1.4426950408889634f

// ---------------- device scratch ----------------
__device__ __half g_h16[(size_t)N * WFEAT];      // h in fp16 (B operand)
__device__ float g_fsrc[N];
__device__ float g_fdst[N];
__device__ float g_rowC[N];
__device__ uint32_t g_mask[(size_t)N * 256];     // packed (adj+self)>0, 8MB
__device__ float g_pmax[256 * WFEAT];            // per-CTA column maxima

// ---------------- helpers ----------------
__device__ __forceinline__ uint32_t smem_u32(const void* p) {
    uint32_t a;
    asm("{ .reg .u64 t; cvta.to.shared.u64 t, %1; cvt.u32.u64 %0, t; }" : "=r"(a) : "l"(p));
    return a;
}
__device__ __forceinline__ void cp16(uint32_t dst, const void* src) {
    asm volatile("cp.async.cg.shared.global [%0], [%1], 16;" :: "r"(dst), "l"(src));
}
__device__ __forceinline__ void cp_commit() {
    asm volatile("cp.async.commit_group;");
}
__device__ __forceinline__ void cp_wait0() {
    asm volatile("cp.async.wait_group 0;");
}
__device__ __forceinline__ void ldsm_x4(uint32_t* r, uint32_t addr) {
    asm volatile("ldmatrix.sync.aligned.m8n8.x4.shared.b16 {%0,%1,%2,%3}, [%4];"
                 : "=r"(r[0]), "=r"(r[1]), "=r"(r[2]), "=r"(r[3]) : "r"(addr));
}
__device__ __forceinline__ void ldsm_x4_t(uint32_t* r, uint32_t addr) {
    asm volatile("ldmatrix.sync.aligned.m8n8.x4.trans.shared.b16 {%0,%1,%2,%3}, [%4];"
                 : "=r"(r[0]), "=r"(r[1]), "=r"(r[2]), "=r"(r[3]) : "r"(addr));
}
__device__ __forceinline__ void mma_f16(float* d, const uint32_t* a, const uint32_t* b) {
    asm volatile(
        "mma.sync.aligned.m16n8k16.row.col.f32.f16.f16.f32 "
        "{%0,%1,%2,%3}, {%4,%5,%6,%7}, {%8,%9}, {%0,%1,%2,%3};"
        : "+f"(d[0]), "+f"(d[1]), "+f"(d[2]), "+f"(d[3])
        : "r"(a[0]), "r"(a[1]), "r"(a[2]), "r"(a[3]), "r"(b[0]), "r"(b[1]));
}

// ---------------- K1: h = emb[inSen] @ W (fp16 h + f_src/f_dst) ----------------
__global__ __launch_bounds__(128) void k1_proj(const int* __restrict__ inSen,
                                               const float* __restrict__ emb,
                                               const float* __restrict__ W,
                                               const float* __restrict__ a_src,
                                               const float* __restrict__ a_dst) {
    __shared__ float Ws[64][128];
    __shared__ float wv[16][64];
    __shared__ int   sIdx[16];
    __shared__ float sa[128], sd[128];

    const int tid = threadIdx.x;
    const int i0  = blockIdx.x * 16;

    if (tid < 16) sIdx[tid] = inSen[i0 + tid];
    sa[tid] = a_src[tid];
    sd[tid] = a_dst[tid];
    __syncthreads();

    float acc[16];
#pragma unroll
    for (int r = 0; r < 16; r++) acc[r] = 0.f;

    const int r  = tid >> 3;
    const int p0 = (tid & 7) * 8;

    for (int kc = 0; kc < EDIM; kc += 64) {
#pragma unroll 8
        for (int dd = 0; dd < 64; dd++)
            Ws[dd][tid] = W[(size_t)(kc + dd) * WFEAT + tid];
        {
            const float* er = emb + (size_t)sIdx[r] * EDIM + kc;
#pragma unroll
            for (int p = 0; p < 8; p++) wv[r][p0 + p] = er[p0 + p];
        }
        __syncthreads();
#pragma unroll 16
        for (int dd = 0; dd < 64; dd++) {
            const float w = Ws[dd][tid];
#pragma unroll
            for (int rr = 0; rr < 16; rr++) acc[rr] += wv[rr][dd] * w;
        }
        __syncthreads();
    }
#pragma unroll
    for (int rr = 0; rr < 16; rr++) {
        const float v = acc[rr];
        g_h16[(size_t)(i0 + rr) * WFEAT + tid] = __float2half(v);
        Ws[rr][tid] = v;                 // stage h tile for f_src/f_dst
    }
    __syncthreads();

    // f_src/f_dst: row rr = tid>>3, 16-col segment per thread, 8-lane reduce
    {
        const int rr  = tid >> 3;
        const int seg = (tid & 7) * 16;
        float ps = 0.f, pd = 0.f;
#pragma unroll
        for (int c2 = 0; c2 < 16; c2++) {
            const float hv = Ws[rr][seg + c2];
            ps += hv * sa[seg + c2];
            pd += hv * sd[seg + c2];
        }
#pragma unroll
        for (int off = 1; off < 8; off <<= 1) {
            ps += __shfl_xor_sync(0xffffffffu, ps, off);
            pd += __shfl_xor_sync(0xffffffffu, pd, off);
        }
        if ((tid & 7) == 0) {
            g_fsrc[i0 + rr] = ps;
            g_fdst[i0 + rr] = pd;
        }
    }
}

// ---------------- K2: row stats + packed mask ----------------
__global__ __launch_bounds__(256) void k2_stats(const int* __restrict__ adj,
                                                const int* __restrict__ selfLinkP) {
    const int i   = blockIdx.x;
    const int tid = threadIdx.x;
    const int lane = tid & 31;
    const int selfLink = *selfLinkP;
    const float si = g_fsrc[i];

    const int4* arow = (const int4*)(adj + (size_t)i * N);
    int4 aa[8];
    float4 ff[8];
#pragma unroll
    for (int k = 0; k < 8; k++) aa[k] = __ldg(arow + tid + (k << 8));
#pragma unroll
    for (int k = 0; k < 8; k++) ff[k] = __ldg((const float4*)&g_fdst[(tid + (k << 8)) << 2]);

    float tm = NEGINF;
#pragma unroll
    for (int k = 0; k < 8; k++) {
        const int idx4 = tid + (k << 8);
        const int j0 = idx4 << 2;
        const int m0 = aa[k].x + ((j0 + 0) == i ? selfLink : 0);
        const int m1 = aa[k].y + ((j0 + 1) == i ? selfLink : 0);
        const int m2 = aa[k].z + ((j0 + 2) == i ? selfLink : 0);
        const int m3 = aa[k].w + ((j0 + 3) == i ? selfLink : 0);

        float x0 = si + ff[k].x, x1 = si + ff[k].y, x2 = si + ff[k].z, x3 = si + ff[k].w;
        x0 = fmaxf(x0, SLOPE * x0);
        x1 = fmaxf(x1, SLOPE * x1);
        x2 = fmaxf(x2, SLOPE * x2);
        x3 = fmaxf(x3, SLOPE * x3);
        const float val0 = (m0 > 0) ? x0 : -1e9f;
        const float val1 = (m1 > 0) ? x1 : -1e9f;
        const float val2 = (m2 > 0) ? x2 : -1e9f;
        const float val3 = (m3 > 0) ? x3 : -1e9f;
        tm = fmaxf(tm, fmaxf(fmaxf(val0, val1), fmaxf(val2, val3)));

        uint32_t wp = ((uint32_t)(m0 > 0) | ((uint32_t)(m1 > 0) << 1) |
                       ((uint32_t)(m2 > 0) << 2) | ((uint32_t)(m3 > 0) << 3))
                      << ((lane & 7) * 4);
        wp |= __shfl_xor_sync(0xffffffffu, wp, 1);
        wp |= __shfl_xor_sync(0xffffffffu, wp, 2);
        wp |= __shfl_xor_sync(0xffffffffu, wp, 4);
        if ((lane & 7) == 0)
            g_mask[(size_t)i * 256 + (idx4 >> 3)] = wp;
    }
    __shared__ float smax[8];
#pragma unroll
    for (int off = 16; off > 0; off >>= 1) tm = fmaxf(tm, __shfl_xor_sync(0xffffffffu, tm, off));
    if ((tid & 31) == 0) smax[tid >> 5] = tm;
    __syncthreads();
    if (tid < 32) {
        float z = (tid < 8) ? smax[tid] : NEGINF;
#pragma unroll
        for (int off = 4; off > 0; off >>= 1) z = fmaxf(z, __shfl_xor_sync(0xffffffffu, z, off));
        if (tid == 0) smax[0] = z;
    }
    __syncthreads();
    const float M = smax[0];

    float ts = 0.f;
#pragma unroll
    for (int k = 0; k < 8; k++) {
        const int j0 = (tid + (k << 8)) << 2;
        const int m0 = aa[k].x + ((j0 + 0) == i ? selfLink : 0);
        const int m1 = aa[k].y + ((j0 + 1) == i ? selfLink : 0);
        const int m2 = aa[k].z + ((j0 + 2) == i ? selfLink : 0);
        const int m3 = aa[k].w + ((j0 + 3) == i ? selfLink : 0);
        float x0 = si + ff[k].x, x1 = si + ff[k].y, x2 = si + ff[k].z, x3 = si + ff[k].w;
        x0 = fmaxf(x0, SLOPE * x0);
        x1 = fmaxf(x1, SLOPE * x1);
        x2 = fmaxf(x2, SLOPE * x2);
        x3 = fmaxf(x3, SLOPE * x3);
        ts += __expf(((m0 > 0) ? x0 : -1e9f) - M);
        ts += __expf(((m1 > 0) ? x1 : -1e9f) - M);
        ts += __expf(((m2 > 0) ? x2 : -1e9f) - M);
        ts += __expf(((m3 > 0) ? x3 : -1e9f) - M);
    }
    __shared__ float ssum[8];
#pragma unroll
    for (int off = 16; off > 0; off >>= 1) ts += __shfl_xor_sync(0xffffffffu, ts, off);
    if ((tid & 31) == 0) ssum[tid >> 5] = ts;
    __syncthreads();
    if (tid == 0) {
        float S = 0.f;
#pragma unroll
        for (int w = 0; w < 8; w++) S += ssum[w];
        g_rowC[i] = fmaf(-M, L2E, -__log2f(S));
    }
}

// ---------------- K3: fp16 1-term pipelined bitmask attention + HMMA ----------------
// smem (bytes): B ring 2 stages [0, 2*17408); A double [34816, +2*4608)
#define B_BUF 17408
#define SB_STRIDE 136
#define OFF_A 34816
#define A_BUF 4608
#define SA_STRIDE 72
#define K3_SMEM 44032
#define NCH (N / 64)

// stage-A for chunk cc -> A fp16 buffer (+att global write); operands pre-loaded
__device__ __forceinline__ void stage_a(char* smem, uint32_t aBufOff, int cc,
                                        float fs, float Cr,
                                        float* att_row, uint2 mw,
                                        float4 d4a, float4 d4b,
                                        int arow, int acol) {
    const int jbase = cc * 64;
#pragma unroll
    for (int g = 0; g < 2; g++) {
        const int jcol = acol + g * 4;
        const int jg = jbase + jcol;
        const uint32_t w = (jcol & 32) ? mw.y : mw.x;
        const int sh = jcol & 31;
        const float4 d4 = g ? d4b : d4a;

        float v0 = fs + d4.x, v1 = fs + d4.y, v2 = fs + d4.z, v3 = fs + d4.w;
        v0 = fmaxf(v0, SLOPE * v0);
        v1 = fmaxf(v1, SLOPE * v1);
        v2 = fmaxf(v2, SLOPE * v2);
        v3 = fmaxf(v3, SLOPE * v3);
        float r0 = (w & (1u << (sh + 0))) ? fmaf(v0, L2E, Cr) : -1e30f;
        float r1 = (w & (1u << (sh + 1))) ? fmaf(v1, L2E, Cr) : -1e30f;
        float r2 = (w & (1u << (sh + 2))) ? fmaf(v2, L2E, Cr) : -1e30f;
        float r3 = (w & (1u << (sh + 3))) ? fmaf(v3, L2E, Cr) : -1e30f;
        float a0, a1, a2, a3;
        asm("ex2.approx.f32 %0, %1;" : "=f"(a0) : "f"(r0));
        asm("ex2.approx.f32 %0, %1;" : "=f"(a1) : "f"(r1));
        asm("ex2.approx.f32 %0, %1;" : "=f"(a2) : "f"(r2));
        asm("ex2.approx.f32 %0, %1;" : "=f"(a3) : "f"(r3));

        __stcs((float4*)(att_row + jg), make_float4(a0, a1, a2, a3));

        __half2 p01 = __floats2half2_rn(a0, a1);
        __half2 p23 = __floats2half2_rn(a2, a3);
        const uint32_t ao = (arow * SA_STRIDE + jcol) * 2;
        *(uint2*)(smem + aBufOff + ao) =
            make_uint2(*(uint32_t*)&p01, *(uint32_t*)&p23);
    }
}

__global__ __launch_bounds__(256, 2) void k3_hmma(float* __restrict__ att_out,
                                                  float* __restrict__ sen_out) {
    extern __shared__ char smem[];
    const uint32_t sb = smem_u32(smem);

    const int tid = threadIdx.x;
    const int wid = tid >> 5;
    const int lane = tid & 31;
    const int i0 = blockIdx.x * 32;

    // stage-A mapping: 8 threads per row, 8 cols each
    const int arow = tid >> 3;
    const int acol = (tid & 7) * 8;
    const int gi = i0 + arow;
    const float fs = g_fsrc[gi];
    const float Cr = g_rowC[gi];
    float* att_row = att_out + (size_t)gi * N;
    const uint2* mrow = (const uint2*)(g_mask + (size_t)gi * 256);

    // B cp.async mapping
    const int cprowB = tid >> 4;
    const int cpsegB = tid & 15;

    // MMA warp tiling
    const int warp_m = wid >> 2;
    const int warp_n = wid & 3;
    const int lrow = lane & 15;
    const int lgrp = lane >> 4;
    const uint32_t a_lane_off = ((warp_m * 16 + lrow) * SA_STRIDE + lgrp * 8) * 2;
    const uint32_t b_lane_off = (lrow * SB_STRIDE + warp_n * 32 + lgrp * 8) * 2;

    float acc[4][4];
#pragma unroll
    for (int nf = 0; nf < 4; nf++)
#pragma unroll
        for (int q = 0; q < 4; q++) acc[nf][q] = 0.f;

    // ---- prologue: prefetch B(0) into stage 0; stage-A(0) into A buf 0 ----
#pragma unroll
    for (int p = 0; p < 4; p++) {
        const int r = cprowB + p * 16;
        cp16(sb + r * 272 + cpsegB * 16,
             (const char*)g_h16 + ((size_t)r * WFEAT + cpsegB * 8) * 2);
    }
    cp_commit();
    {
        const uint2 mw0 = __ldg(&mrow[0]);
        const float4 d4a0 = __ldg((const float4*)&g_fdst[acol]);
        const float4 d4b0 = __ldg((const float4*)&g_fdst[acol + 4]);
        stage_a(smem, OFF_A, 0, fs, Cr, att_row, mw0, d4a0, d4b0, arow, acol);
    }

#pragma unroll 2
    for (int c = 0; c < NCH; c++) {
        const int b = c & 1;

        cp_wait0();        // own share of B(c) landed
        __syncthreads();   // all shares + A[b] visible; MMA(c-1) done -> buffers free

        // --- register-prefetch stage-A(c+1) operands (latency hidden by MMA) ---
        uint2 mw_n = make_uint2(0u, 0u);
        float4 d4a_n = make_float4(0.f, 0.f, 0.f, 0.f);
        float4 d4b_n = d4a_n;
        if (c + 1 < NCH) {
            mw_n  = __ldg(&mrow[c + 1]);
            d4a_n = __ldg((const float4*)&g_fdst[(c + 1) * 64 + acol]);
            d4b_n = __ldg((const float4*)&g_fdst[(c + 1) * 64 + acol + 4]);
        }

        // --- prefetch B(c+1) into stage 1-b (last read by MMA(c-1)) ---
        if (c + 1 < NCH) {
            const int jb = (c + 1) * 64;
            const uint32_t bs = sb + (1 - b) * B_BUF;
#pragma unroll
            for (int p = 0; p < 4; p++) {
                const int r = cprowB + p * 16;
                cp16(bs + r * 272 + cpsegB * 16,
                     (const char*)g_h16 + ((size_t)(jb + r) * WFEAT + cpsegB * 8) * 2);
            }
        }
        cp_commit();

        // --- MMA(c): A from buf b, B from stage b ---
        const uint32_t a_hi = sb + OFF_A + b * A_BUF + a_lane_off;
        const uint32_t bh_base = sb + b * B_BUF + b_lane_off;
#pragma unroll
        for (int ks = 0; ks < 4; ks++) {
            uint32_t ah[4], bh[2][4];
            ldsm_x4(ah, a_hi + (ks * 16) * 2);
#pragma unroll
            for (int pr = 0; pr < 2; pr++) {
                const uint32_t boff = (ks * 16 * SB_STRIDE + pr * 16) * 2;
                ldsm_x4_t(bh[pr], bh_base + boff);
            }
#pragma unroll
            for (int nf = 0; nf < 4; nf++)
                mma_f16(acc[nf], ah, &bh[nf >> 1][(nf & 1) * 2]);
        }

        // --- stage-A(c+1) into A buf 1-b (last read by MMA(c-1)) ---
        if (c + 1 < NCH)
            stage_a(smem, OFF_A + (1 - b) * A_BUF, c + 1, fs, Cr,
                    att_row, mw_n, d4a_n, d4b_n, arow, acol);
    }

    // --- epilogue: sentence tile + fused column-max pooling ---
    const int grp = lane >> 2;
    const int tig = lane & 3;
    float cmax[4][2];
#pragma unroll
    for (int nf = 0; nf < 4; nf++) {
        const int row0 = i0 + warp_m * 16 + grp;
        const int col  = warp_n * 32 + nf * 8 + tig * 2;
        __stcs((float2*)&sen_out[(size_t)row0 * WFEAT + col],
               make_float2(acc[nf][0], acc[nf][1]));
        __stcs((float2*)&sen_out[(size_t)(row0 + 8) * WFEAT + col],
               make_float2(acc[nf][2], acc[nf][3]));
        cmax[nf][0] = fmaxf(acc[nf][0], acc[nf][2]);
        cmax[nf][1] = fmaxf(acc[nf][1], acc[nf][3]);
    }
#pragma unroll
    for (int off = 4; off <= 16; off <<= 1)
#pragma unroll
        for (int nf = 0; nf < 4; nf++) {
            cmax[nf][0] = fmaxf(cmax[nf][0], __shfl_xor_sync(0xffffffffu, cmax[nf][0], off));
            cmax[nf][1] = fmaxf(cmax[nf][1], __shfl_xor_sync(0xffffffffu, cmax[nf][1], off));
        }
    __syncthreads();
    float* pm = (float*)smem;              // pm[2][128]
    if (grp == 0) {
#pragma unroll
        for (int nf = 0; nf < 4; nf++) {
            pm[warp_m * 128 + warp_n * 32 + nf * 8 + tig * 2]     = cmax[nf][0];
            pm[warp_m * 128 + warp_n * 32 + nf * 8 + tig * 2 + 1] = cmax[nf][1];
        }
    }
    __syncthreads();
    if (tid < 128)
        g_pmax[blockIdx.x * WFEAT + tid] = fmaxf(pm[tid], pm[128 + tid]);
}

// ---------------- K5: final pool + classifier (parallelized reduce) ----------------
__global__ __launch_bounds__(1024) void k5_head(const float* __restrict__ cls_W,
                                                const float* __restrict__ cls_b,
                                                float* __restrict__ pool_out,
                                                float* __restrict__ lab_out) {
    const int tid  = threadIdx.x;
    const int col  = tid & 127;
    const int part = tid >> 7;              // 0..7
    __shared__ float pp[8][WFEAT];
    __shared__ float pool[WFEAT];

    float m = NEGINF;
    const int b0 = part * 32;
#pragma unroll 8
    for (int b = 0; b < 32; b++)
        m = fmaxf(m, __ldg(&g_pmax[(b0 + b) * WFEAT + col]));
    pp[part][col] = m;
    __syncthreads();

    if (tid < 128) {
        float mm = pp[0][tid];
#pragma unroll
        for (int p = 1; p < 8; p++) mm = fmaxf(mm, pp[p][tid]);
        pool[tid] = mm;
        pool_out[tid] = mm;
    }
    __syncthreads();

    if (tid < 32) {
        float l0 = 0.f, l1 = 0.f;
#pragma unroll
        for (int q = 0; q < 4; q++) {
            const int k = tid * 4 + q;
            const float pv = pool[k];
            l0 += pv * __ldg(&cls_W[2 * k]);
            l1 += pv * __ldg(&cls_W[2 * k + 1]);
        }
#pragma unroll
        for (int off = 16; off > 0; off >>= 1) {
            l0 += __shfl_xor_sync(0xffffffffu, l0, off);
            l1 += __shfl_xor_sync(0xffffffffu, l1, off);
        }
        if (tid == 0) {
            l0 += __ldg(&cls_b[0]);
            l1 += __ldg(&cls_b[1]);
            const float mm = fmaxf(l0, l1);
            const float e0 = __expf(l0 - mm), e1 = __expf(l1 - mm);
            const float inv = 1.0f / (e0 + e1);
            lab_out[0] = e0 * inv;
            lab_out[1] = e1 * inv;
        }
    }
}

// ---------------- launch ----------------
extern "C" void kernel_launch(void* const* d_in, const int* in_sizes, int n_in,
                              void* d_out, int out_size) {
    const int*   inSen    = (const int*)d_in[0];
    const int*   adj      = (const int*)d_in[1];
    const int*   selfLink = (const int*)d_in[2];
    const float* emb      = (const float*)d_in[3];
    const float* W        = (const float*)d_in[4];
    const float* a_src    = (const float*)d_in[5];
    const float* a_dst    = (const float*)d_in[6];
    const float* cls_W    = (const float*)d_in[7];
    const float* cls_b    = (const float*)d_in[8];

    float* out      = (float*)d_out;
    float* pool_out = out;
    float* att_out  = out + WFEAT;
    float* sen_out  = att_out + (size_t)N * N;
    float* lab_out  = sen_out + (size_t)N * WFEAT;

    static int configured = 0;
    if (!configured) {
        cudaFuncSetAttribute(k3_hmma, cudaFuncAttributeMaxDynamicSharedMemorySize, K3_SMEM);
        configured = 1;
    }

    k1_proj<<<N / 16, 128>>>(inSen, emb, W, a_src, a_dst);
    k2_stats<<<N, 256>>>(adj, selfLink);
    k3_hmma<<<N / 32, 256, K3_SMEM>>>(att_out, sen_out);
    k5_head<<<1, 1024>>>(cls_W, cls_b, pool_out, lab_out);
}